// round 6
// baseline (speedup 1.0000x reference)
#include <cuda_runtime.h>
#include <math.h>
#include <stdint.h>

// Problem constants
#define NT   4096
#define DD   1024
#define SS   2048
#define NHQ  16
#define NHKV 4
#define DH   64
#define KVD  (NHKV * DH)   // 256
#define FF   2048
#define NEXP 8
#define EPS_RMS 1e-5f

#define BM 256
#define BN 128
#define BK 16

// dynamic smem for sgemm: As 2*BK*BM floats, then Bs2 2*BK*BN float2
#define SGEMM_SMEM ((2 * BK * BM) * 4 + (2 * BK * BN) * 8)   // 65536 B

typedef unsigned long long ull;

// packed fp32x2 helpers (Blackwell fma.rn.f32x2 — 2 MACs per issue on fma pipe)
__device__ __forceinline__ ull pk2(float x, float y) {
    ull r; asm("mov.b64 %0, {%1, %2};" : "=l"(r) : "f"(x), "f"(y)); return r;
}
__device__ __forceinline__ void fma2(ull& c, ull a, ull b) {
    asm("fma.rn.f32x2 %0, %1, %2, %0;" : "+l"(c) : "l"(a), "l"(b));
}
__device__ __forceinline__ float2 up2(ull v) {
    float2 r; asm("mov.b64 {%0, %1}, %2;" : "=f"(r.x), "=f"(r.y) : "l"(v)); return r;
}

// ---------------------------------------------------------------------------
// Scratch (device globals; allocation-free). 16B-aligned for float4 access.
// ---------------------------------------------------------------------------
__device__ __align__(16) float g_h1  [(size_t)NT * DD];
__device__ __align__(16) float g_q   [(size_t)NT * DD];
__device__ __align__(16) float g_k   [(size_t)NT * KVD];
__device__ __align__(16) float g_v   [(size_t)NT * KVD];
__device__ __align__(16) float g_ctx [(size_t)NT * DD];
__device__ __align__(16) float g_attn[(size_t)NT * DD];
__device__ __align__(16) float g_res2[(size_t)NT * DD];
__device__ __align__(16) float g_flat[(size_t)NT * DD];
__device__ __align__(16) float g_G   [(size_t)NEXP * NT * FF];
__device__ __align__(16) float g_U   [(size_t)NEXP * NT * FF];
__device__ __align__(16) float g_O   [(size_t)NEXP * NT * DD];
__device__ int   g_cnt [NEXP];
__device__ int   g_list[NEXP * NT];
__device__ int   g_tok_e[NT * 2];
__device__ int   g_tok_i[NT * 2];
__device__ float g_tok_w[NT * 2];
__device__ float g_invf[32];

// ---------------------------------------------------------------------------
__global__ void k_zero_init() {
    int i = threadIdx.x;
    if (i < NEXP) g_cnt[i] = 0;
    if (i < 32) {
        double ex = -((double)(2 * i) / 64.0) * 13.28771237954944939; // log2(1e4)
        g_invf[i] = (float)exp2(ex);
    }
}

// ---------------------------------------------------------------------------
// RMSNorm 1
// ---------------------------------------------------------------------------
__global__ void __launch_bounds__(256) k_rms1(const float* __restrict__ x,
                                              const float* __restrict__ w) {
    int t = blockIdx.x, i = threadIdx.x;
    float4 v = ((const float4*)(x + (size_t)t * DD))[i];
    float ss = v.x * v.x + v.y * v.y + v.z * v.z + v.w * v.w;
    __shared__ float red[8];
    int lane = i & 31, wp = i >> 5;
    #pragma unroll
    for (int o = 16; o; o >>= 1) ss += __shfl_xor_sync(0xffffffffu, ss, o);
    if (!lane) red[wp] = ss;
    __syncthreads();
    if (i == 0) { float s = 0.f; for (int j = 0; j < 8; j++) s += red[j]; red[0] = s; }
    __syncthreads();
    float rs = rsqrtf(red[0] * (1.0f / DD) + EPS_RMS);
    float4 wv = ((const float4*)w)[i];
    ((float4*)(g_h1 + (size_t)t * DD))[i] =
        make_float4(v.x * rs * wv.x, v.y * rs * wv.y, v.z * rs * wv.z, v.w * rs * wv.w);
}

// ---------------------------------------------------------------------------
// SGEMM core: 256x128x16 tile, 256 threads, 16Mx8N per thread, packed FFMA2.
// B tile stored DUPLICATED in smem ((b,b) float2 pairs) so the inner loop has
// zero pack MOVs: 8x LDS.128 + 64x FFMA2 per kk per thread.
// Tiles live in DYNAMIC smem (64KB > 48KB static cap).
// ---------------------------------------------------------------------------
__device__ __forceinline__ void sgemm_core(
    const float* a0, const float* a1, const float* a2r, const float* a3,
    const float* __restrict__ B, int ldb, int bcol,
    float* __restrict__ C, int ldc, int ccol,
    int Kd, int Me, int m0)
{
    extern __shared__ float smf[];
    float*  As  = smf;                            // [2][BK][BM]
    float2* Bs2 = (float2*)(smf + 2 * BK * BM);   // [2][BK][BN]

    int tid = threadIdx.x;
    int ar = tid >> 2, ac4 = tid & 3;        // A loader: rows ar+64q, k-quad ac4
    int brow = tid >> 4, bq = tid & 15;      // B loader: k-row brow, col-quads bq, bq+16
    int tr = tid >> 4, tx = tid & 15;        // compute: rows tr*16..+15, cols tx*8..+7

    const float* ap[4] = {a0, a1, a2r, a3};

    ull acc[8][8];
    #pragma unroll
    for (int i = 0; i < 8; i++)
        #pragma unroll
        for (int j = 0; j < 8; j++) acc[i][j] = 0ull;

    int nk = Kd / BK;
    float4 va[4], vb[2];

    // prologue: tile 0
    #pragma unroll
    for (int q = 0; q < 4; q++) va[q] = *(const float4*)(ap[q] + ac4 * 4);
    vb[0] = *(const float4*)(B + (size_t)brow * ldb + bcol + bq * 4);
    vb[1] = *(const float4*)(B + (size_t)brow * ldb + bcol + (bq + 16) * 4);
    #pragma unroll
    for (int q = 0; q < 4; q++) {
        As[(ac4 * 4 + 0) * BM + ar + 64 * q] = va[q].x;
        As[(ac4 * 4 + 1) * BM + ar + 64 * q] = va[q].y;
        As[(ac4 * 4 + 2) * BM + ar + 64 * q] = va[q].z;
        As[(ac4 * 4 + 3) * BM + ar + 64 * q] = va[q].w;
    }
    *(float4*)&Bs2[brow * BN + bq * 4 + 0]        = make_float4(vb[0].x, vb[0].x, vb[0].y, vb[0].y);
    *(float4*)&Bs2[brow * BN + bq * 4 + 2]        = make_float4(vb[0].z, vb[0].z, vb[0].w, vb[0].w);
    *(float4*)&Bs2[brow * BN + (bq + 16) * 4 + 0] = make_float4(vb[1].x, vb[1].x, vb[1].y, vb[1].y);
    *(float4*)&Bs2[brow * BN + (bq + 16) * 4 + 2] = make_float4(vb[1].z, vb[1].z, vb[1].w, vb[1].w);
    __syncthreads();

    for (int kt = 0; kt < nk; kt++) {
        if (kt + 1 < nk) {
            int kn = (kt + 1) * BK;
            #pragma unroll
            for (int q = 0; q < 4; q++) va[q] = *(const float4*)(ap[q] + kn + ac4 * 4);
            vb[0] = *(const float4*)(B + (size_t)(kn + brow) * ldb + bcol + bq * 4);
            vb[1] = *(const float4*)(B + (size_t)(kn + brow) * ldb + bcol + (bq + 16) * 4);
        }
        int st = kt & 1;
        const float*  Asb = As  + st * (BK * BM);
        const float2* Bsb = Bs2 + st * (BK * BN);
        #pragma unroll
        for (int kk = 0; kk < BK; kk++) {
            ull av[8], bd[8];
            *(float4*)&av[0] = *(const float4*)&Asb[kk * BM + tr * 16];
            *(float4*)&av[2] = *(const float4*)&Asb[kk * BM + tr * 16 + 4];
            *(float4*)&av[4] = *(const float4*)&Asb[kk * BM + tr * 16 + 8];
            *(float4*)&av[6] = *(const float4*)&Asb[kk * BM + tr * 16 + 12];
            *(float4*)&bd[0] = *(const float4*)&Bsb[kk * BN + tx * 8 + 0];
            *(float4*)&bd[2] = *(const float4*)&Bsb[kk * BN + tx * 8 + 2];
            *(float4*)&bd[4] = *(const float4*)&Bsb[kk * BN + tx * 8 + 4];
            *(float4*)&bd[6] = *(const float4*)&Bsb[kk * BN + tx * 8 + 6];
            #pragma unroll
            for (int i = 0; i < 8; i++)
                #pragma unroll
                for (int j = 0; j < 8; j++)
                    fma2(acc[i][j], av[i], bd[j]);
        }
        if (kt + 1 < nk) {
            int s2 = (kt + 1) & 1;
            float*  Asn = As  + s2 * (BK * BM);
            float2* Bsn = Bs2 + s2 * (BK * BN);
            #pragma unroll
            for (int q = 0; q < 4; q++) {
                Asn[(ac4 * 4 + 0) * BM + ar + 64 * q] = va[q].x;
                Asn[(ac4 * 4 + 1) * BM + ar + 64 * q] = va[q].y;
                Asn[(ac4 * 4 + 2) * BM + ar + 64 * q] = va[q].z;
                Asn[(ac4 * 4 + 3) * BM + ar + 64 * q] = va[q].w;
            }
            *(float4*)&Bsn[brow * BN + bq * 4 + 0]        = make_float4(vb[0].x, vb[0].x, vb[0].y, vb[0].y);
            *(float4*)&Bsn[brow * BN + bq * 4 + 2]        = make_float4(vb[0].z, vb[0].z, vb[0].w, vb[0].w);
            *(float4*)&Bsn[brow * BN + (bq + 16) * 4 + 0] = make_float4(vb[1].x, vb[1].x, vb[1].y, vb[1].y);
            *(float4*)&Bsn[brow * BN + (bq + 16) * 4 + 2] = make_float4(vb[1].z, vb[1].z, vb[1].w, vb[1].w);
        }
        __syncthreads();
    }

    // epilogue: acc[i][j] holds rows (tr*16+2i, +1), col tx*8+j
    #pragma unroll
    for (int i = 0; i < 8; i++) {
        float c0[8], c1[8];
        #pragma unroll
        for (int j = 0; j < 8; j++) { float2 u = up2(acc[i][j]); c0[j] = u.x; c1[j] = u.y; }
        int r0 = m0 + tr * 16 + 2 * i;
        if (r0 < Me) {
            float* p = C + (size_t)r0 * ldc + ccol + tx * 8;
            *(float4*)p       = make_float4(c0[0], c0[1], c0[2], c0[3]);
            *(float4*)(p + 4) = make_float4(c0[4], c0[5], c0[6], c0[7]);
        }
        if (r0 + 1 < Me) {
            float* p = C + (size_t)(r0 + 1) * ldc + ccol + tx * 8;
            *(float4*)p       = make_float4(c1[0], c1[1], c1[2], c1[3]);
            *(float4*)(p + 4) = make_float4(c1[4], c1[5], c1[6], c1[7]);
        }
    }
}

// General SGEMM (expert batch + gather + runtime M)
__global__ void __launch_bounds__(256, 1) k_sgemm(
    const float* __restrict__ A, const float* __restrict__ B, float* __restrict__ C,
    int M, int N, int Kd,
    const int* __restrict__ rowlist, const int* __restrict__ counts,
    size_t strideAe, size_t strideBe, size_t strideCe)
{
    int e  = blockIdx.z;
    int Me = counts ? counts[e] : M;
    int m0 = blockIdx.y * BM;
    if (m0 >= Me) return;
    int n0 = blockIdx.x * BN;
    const float* Ab = A + (size_t)e * strideAe;
    const float* Bb = B + (size_t)e * strideBe;
    float*       Cb = C + (size_t)e * strideCe;

    int ar = threadIdx.x >> 2;
    const int* lst = rowlist ? (rowlist + e * NT) : (const int*)0;
    const float* ap[4];
    #pragma unroll
    for (int q = 0; q < 4; q++) {
        int r = m0 + ar + 64 * q; if (r > Me - 1) r = Me - 1;
        size_t gr = lst ? (size_t)lst[r] : (size_t)r;
        ap[q] = Ab + gr * (size_t)Kd;
    }
    sgemm_core(ap[0], ap[1], ap[2], ap[3], Bb, N, n0, Cb, N, n0, Kd, Me, m0);
}

// Fused QKV projection: blockIdx.x picks Wq/Wk/Wv column range
__global__ void __launch_bounds__(256, 1) k_sgemm_qkv(
    const float* __restrict__ h1,
    const float* __restrict__ Wq, const float* __restrict__ Wk,
    const float* __restrict__ Wv)
{
    int bx = blockIdx.x;
    int m0 = blockIdx.y * BM;
    const float* B; float* C; int ldb, bcol;
    if (bx < 8)       { B = Wq; C = g_q; ldb = 1024; bcol = bx * 128; }
    else if (bx < 10) { B = Wk; C = g_k; ldb = KVD;  bcol = (bx - 8) * 128; }
    else              { B = Wv; C = g_v; ldb = KVD;  bcol = (bx - 10) * 128; }
    int ar = threadIdx.x >> 2;
    const float* ap[4];
    #pragma unroll
    for (int q = 0; q < 4; q++) ap[q] = h1 + (size_t)(m0 + ar + 64 * q) * DD;
    sgemm_core(ap[0], ap[1], ap[2], ap[3], B, ldb, bcol, C, ldb, bcol, DD, NT, m0);
}

// ---------------------------------------------------------------------------
// RoPE
// ---------------------------------------------------------------------------
__global__ void __launch_bounds__(512) k_rope_q() {
    int t = blockIdx.x;
    int h = threadIdx.x >> 5, i = threadIdx.x & 31;
    int pos = t & (SS - 1);
    float ang = (float)pos * g_invf[i];
    float s, c; sincosf(ang, &s, &c);
    size_t base = (size_t)t * DD + h * DH + i;
    float x1 = g_q[base], x2 = g_q[base + 32];
    g_q[base] = x1 * c - x2 * s;
    g_q[base + 32] = x2 * c + x1 * s;
}
__global__ void __launch_bounds__(128) k_rope_k() {
    int t = blockIdx.x;
    int h = threadIdx.x >> 5, i = threadIdx.x & 31;
    int pos = t & (SS - 1);
    float ang = (float)pos * g_invf[i];
    float s, c; sincosf(ang, &s, &c);
    size_t base = (size_t)t * KVD + h * DH + i;
    float x1 = g_k[base], x2 = g_k[base + 32];
    g_k[base] = x1 * c - x2 * s;
    g_k[base + 32] = x2 * c + x1 * s;
}

// ---------------------------------------------------------------------------
// Causal GQA flash attention with packed FFMA2 dot/pv loops.
// ---------------------------------------------------------------------------
__global__ void __launch_bounds__(128) k_attn() {
    int qt = blockIdx.x;
    int bh = blockIdx.y;
    int b = bh >> 4, h = bh & 15, hk = h >> 2;
    int tid = threadIdx.x;
    extern __shared__ float sm[];
    float* Ks = sm;
    float* Vs = sm + 4096;
    float* Sr = sm + 8192;

    int qi = qt * 128 + tid;
    int t  = b * SS + qi;
    float2 q2[32];
    {
        const float4* qp = (const float4*)(g_q + (size_t)t * DD + h * DH);
        #pragma unroll
        for (int u = 0; u < 16; u++) {
            float4 x = qp[u];
            q2[2 * u]     = make_float2(x.x * 0.125f, x.y * 0.125f);
            q2[2 * u + 1] = make_float2(x.z * 0.125f, x.w * 0.125f);
        }
    }
    float2 a2[32];
    #pragma unroll
    for (int d = 0; d < 32; d++) a2[d] = make_float2(0.f, 0.f);
    float m = -3e38f, l = 0.f;

    int jmax = 2 * qt + 1;
    for (int jt = 0; jt <= jmax; jt++) {
        int kb = b * SS + jt * 64;
        #pragma unroll
        for (int u = 0; u < 8; u++) {
            int lin = u * 128 + tid;
            int row = lin >> 4, c4 = lin & 15;
            *(float4*)(Ks + row * 64 + c4 * 4) =
                *(const float4*)(g_k + (size_t)(kb + row) * KVD + hk * DH + c4 * 4);
            *(float4*)(Vs + row * 64 + c4 * 4) =
                *(const float4*)(g_v + (size_t)(kb + row) * KVD + hk * DH + c4 * 4);
        }
        __syncthreads();
        int lim = qi - jt * 64;
        if (lim >= 0) {
            int cmax = lim < 63 ? lim : 63;
            float smax = -3e38f;
            for (int c = 0; c <= cmax; c++) {
                const float4* kr = (const float4*)(Ks + c * 64);
                ull s2 = 0ull;
                #pragma unroll
                for (int d4 = 0; d4 < 16; d4++) {
                    float4 kv = kr[d4];
                    fma2(s2, *(ull*)&q2[2 * d4],     *(ull*)&kv.x);
                    fma2(s2, *(ull*)&q2[2 * d4 + 1], *(ull*)&kv.z);
                }
                float2 sr = up2(s2);
                float s = sr.x + sr.y;
                Sr[tid * 65 + c] = s;
                smax = fmaxf(smax, s);
            }
            float mnew = fmaxf(m, smax);
            float corr = __expf(m - mnew);
            l *= corr;
            #pragma unroll
            for (int d = 0; d < 32; d++) { a2[d].x *= corr; a2[d].y *= corr; }
            for (int c = 0; c <= cmax; c++) {
                float p = __expf(Sr[tid * 65 + c] - mnew);
                l += p;
                ull pd = pk2(p, p);
                const float4* vr = (const float4*)(Vs + c * 64);
                #pragma unroll
                for (int d4 = 0; d4 < 16; d4++) {
                    float4 vv = vr[d4];
                    fma2(*(ull*)&a2[2 * d4],     *(ull*)&vv.x, pd);
                    fma2(*(ull*)&a2[2 * d4 + 1], *(ull*)&vv.z, pd);
                }
            }
            m = mnew;
        }
        __syncthreads();
    }
    float inv = 1.0f / l;
    float4* op = (float4*)(g_ctx + (size_t)t * DD + h * DH);
    #pragma unroll
    for (int u = 0; u < 16; u++)
        op[u] = make_float4(a2[2 * u].x * inv, a2[2 * u].y * inv,
                            a2[2 * u + 1].x * inv, a2[2 * u + 1].y * inv);
}

// ---------------------------------------------------------------------------
// residual add + clip + RMSNorm2
// ---------------------------------------------------------------------------
__global__ void __launch_bounds__(256) k_post(const float* __restrict__ hidden,
                                              const float* __restrict__ w2) {
    int t = blockIdx.x, i = threadIdx.x;
    float4 hv = ((const float4*)(hidden + (size_t)t * DD))[i];
    float4 av = ((const float4*)(g_attn + (size_t)t * DD))[i];
    float4 s;
    s.x = fminf(fmaxf(hv.x + av.x, -100.f), 100.f);
    s.y = fminf(fmaxf(hv.y + av.y, -100.f), 100.f);
    s.z = fminf(fmaxf(hv.z + av.z, -100.f), 100.f);
    s.w = fminf(fmaxf(hv.w + av.w, -100.f), 100.f);
    ((float4*)(g_res2 + (size_t)t * DD))[i] = s;
    float ss = s.x * s.x + s.y * s.y + s.z * s.z + s.w * s.w;
    __shared__ float red[8];
    int lane = i & 31, wp = i >> 5;
    #pragma unroll
    for (int o = 16; o; o >>= 1) ss += __shfl_xor_sync(0xffffffffu, ss, o);
    if (!lane) red[wp] = ss;
    __syncthreads();
    if (i == 0) { float z = 0.f; for (int j = 0; j < 8; j++) z += red[j]; red[0] = z; }
    __syncthreads();
    float rs = rsqrtf(red[0] * (1.0f / DD) + EPS_RMS);
    float4 wv = ((const float4*)w2)[i];
    ((float4*)(g_flat + (size_t)t * DD))[i] =
        make_float4(s.x * rs * wv.x, s.y * rs * wv.y, s.z * rs * wv.z, s.w * rs * wv.w);
}

// ---------------------------------------------------------------------------
// Router
// ---------------------------------------------------------------------------
__global__ void __launch_bounds__(256) k_router(const float* __restrict__ Wr) {
    int t = blockIdx.x;
    int lane = threadIdx.x & 31, w = threadIdx.x >> 5;
    const float* fr = g_flat + (size_t)t * DD;
    float s = 0.f;
    for (int d = lane; d < DD; d += 32) s += fr[d] * Wr[d * NEXP + w];
    #pragma unroll
    for (int o = 16; o; o >>= 1) s += __shfl_xor_sync(0xffffffffu, s, o);
    __shared__ float lg[NEXP];
    if (!lane) lg[w] = s;
    __syncthreads();
    if (threadIdx.x == 0) {
        float l0 = -3e38f; int i0 = 0;
        #pragma unroll
        for (int e2 = 0; e2 < NEXP; e2++) if (lg[e2] > l0) { l0 = lg[e2]; i0 = e2; }
        float l1 = -3e38f; int i1 = 0;
        #pragma unroll
        for (int e2 = 0; e2 < NEXP; e2++)
            if (e2 != i0 && lg[e2] > l1) { l1 = lg[e2]; i1 = e2; }
        float p1 = __expf(l1 - l0);
        float w0 = 1.0f / (1.0f + p1), w1 = p1 / (1.0f + p1);
        int pos0 = atomicAdd(&g_cnt[i0], 1);
        g_list[i0 * NT + pos0] = t;
        g_tok_e[t * 2] = i0; g_tok_i[t * 2] = pos0; g_tok_w[t * 2] = w0;
        int pos1 = atomicAdd(&g_cnt[i1], 1);
        g_list[i1 * NT + pos1] = t;
        g_tok_e[t * 2 + 1] = i1; g_tok_i[t * 2 + 1] = pos1; g_tok_w[t * 2 + 1] = w1;
    }
}

// ---------------------------------------------------------------------------
// SiLU(g)*u in place into g_G
// ---------------------------------------------------------------------------
__global__ void __launch_bounds__(256) k_act() {
    int e = blockIdx.y, r = blockIdx.x;
    if (r >= g_cnt[e]) return;
    size_t base4 = (((size_t)e * NT + r) * FF) >> 2;
    float4* G4 = (float4*)g_G;
    const float4* U4 = (const float4*)g_U;
    for (int f = threadIdx.x; f < FF / 4; f += 256) {
        float4 g = G4[base4 + f], u = U4[base4 + f];
        g.x = g.x / (1.f + __expf(-g.x)) * u.x;
        g.y = g.y / (1.f + __expf(-g.y)) * u.y;
        g.z = g.z / (1.f + __expf(-g.z)) * u.z;
        g.w = g.w / (1.f + __expf(-g.w)) * u.w;
        G4[base4 + f] = g;
    }
}

// ---------------------------------------------------------------------------
// Final combine
// ---------------------------------------------------------------------------
__global__ void __launch_bounds__(256) k_combine(float* __restrict__ out) {
    int t = blockIdx.x, i = threadIdx.x;
    int e0 = g_tok_e[t * 2],     i0 = g_tok_i[t * 2];     float w0 = g_tok_w[t * 2];
    int e1 = g_tok_e[t * 2 + 1], i1 = g_tok_i[t * 2 + 1]; float w1 = g_tok_w[t * 2 + 1];
    const float4* o0 = (const float4*)(g_O + ((size_t)e0 * NT + i0) * DD);
    const float4* o1 = (const float4*)(g_O + ((size_t)e1 * NT + i1) * DD);
    const float4* rr = (const float4*)(g_res2 + (size_t)t * DD);
    float4 a = rr[i], x = o0[i], y = o1[i], o;
    o.x = fminf(fmaxf(a.x + w0 * x.x + w1 * y.x, -100.f), 100.f);
    o.y = fminf(fmaxf(a.y + w0 * x.y + w1 * y.y, -100.f), 100.f);
    o.z = fminf(fmaxf(a.z + w0 * x.z + w1 * y.z, -100.f), 100.f);
    o.w = fminf(fmaxf(a.w + w0 * x.w + w1 * y.w, -100.f), 100.f);
    ((float4*)(out + (size_t)t * DD))[i] = o;
}

// ---------------------------------------------------------------------------
// Host launcher
// ---------------------------------------------------------------------------
extern "C" void kernel_launch(void* const* d_in, const int* in_sizes, int n_in,
                              void* d_out, int out_size) {
    const float* hidden = (const float*)d_in[0];
    const float* ln1    = (const float*)d_in[1];
    const float* ln2    = (const float*)d_in[2];
    const float* Wq     = (const float*)d_in[3];
    const float* Wk     = (const float*)d_in[4];
    const float* Wv     = (const float*)d_in[5];
    const float* Wo     = (const float*)d_in[6];
    const float* Wr     = (const float*)d_in[7];
    const float* Wg     = (const float*)d_in[8];
    const float* Wu     = (const float*)d_in[9];
    const float* Wd     = (const float*)d_in[10];
    float* out = (float*)d_out;
    (void)in_sizes; (void)n_in; (void)out_size;

    float *p_h1, *p_ctx, *p_attn, *p_flat, *p_G, *p_U, *p_O;
    int *p_lst, *p_cnt;
    cudaGetSymbolAddress((void**)&p_h1,  g_h1);
    cudaGetSymbolAddress((void**)&p_ctx, g_ctx);
    cudaGetSymbolAddress((void**)&p_attn,g_attn);
    cudaGetSymbolAddress((void**)&p_flat,g_flat);
    cudaGetSymbolAddress((void**)&p_G,   g_G);
    cudaGetSymbolAddress((void**)&p_U,   g_U);
    cudaGetSymbolAddress((void**)&p_O,   g_O);
    cudaGetSymbolAddress((void**)&p_lst, g_list);
    cudaGetSymbolAddress((void**)&p_cnt, g_cnt);

    const int ATTN_SMEM = (4096 + 4096 + 128 * 65) * 4;   // 66048 B
    static int s_attr_done = 0;
    if (!s_attr_done) {
        cudaFuncSetAttribute(k_attn, cudaFuncAttributeMaxDynamicSharedMemorySize, ATTN_SMEM);
        cudaFuncSetAttribute(k_sgemm, cudaFuncAttributeMaxDynamicSharedMemorySize, SGEMM_SMEM);
        cudaFuncSetAttribute(k_sgemm_qkv, cudaFuncAttributeMaxDynamicSharedMemorySize, SGEMM_SMEM);
        s_attr_done = 1;
    }

    k_zero_init<<<1, 32>>>();
    k_rms1<<<NT, 256>>>(hidden, ln1);

    // Fused QKV projection
    k_sgemm_qkv<<<dim3(12, NT / BM), 256, SGEMM_SMEM>>>(p_h1, Wq, Wk, Wv);

    k_rope_q<<<NT, 512>>>();
    k_rope_k<<<NT, 128>>>();

    k_attn<<<dim3(16, 32), 128, ATTN_SMEM>>>();

    // Wo projection
    k_sgemm<<<dim3(8, NT / BM, 1), 256, SGEMM_SMEM>>>((const float*)p_ctx, Wo, p_attn,
                                          NT, 1024, 1024, 0, 0, 0, 0, 0);

    k_post<<<NT, 256>>>(hidden, ln2);
    k_router<<<NT, 256>>>(Wr);

    // Expert FFN
    k_sgemm<<<dim3(16, NT / BM, NEXP), 256, SGEMM_SMEM>>>((const float*)p_flat, Wg, p_G, 0, FF, DD,
                                              p_lst, p_cnt, 0, (size_t)DD * FF, (size_t)NT * FF);
    k_sgemm<<<dim3(16, NT / BM, NEXP), 256, SGEMM_SMEM>>>((const float*)p_flat, Wu, p_U, 0, FF, DD,
                                              p_lst, p_cnt, 0, (size_t)DD * FF, (size_t)NT * FF);
    k_act<<<dim3(NT, NEXP), 256>>>();
    k_sgemm<<<dim3(8, NT / BM, NEXP), 256, SGEMM_SMEM>>>((const float*)p_G, Wd, p_O, 0, DD, FF,
                                             0, p_cnt, (size_t)NT * FF, (size_t)FF * DD, (size_t)NT * DD);

    k_combine<<<NT, 256>>>(out);
}

// round 7
// speedup vs baseline: 1.4856x; 1.4856x over previous
#include <cuda_runtime.h>
#include <math.h>
#include <stdint.h>

// Problem constants
#define NT   4096
#define DD   1024
#define SS   2048
#define NHQ  16
#define NHKV 4
#define DH   64
#define KVD  (NHKV * DH)   // 256
#define FF   2048
#define NEXP 8
#define EPS_RMS 1e-5f

#define BM 256
#define BN 128
#define BK 16

// dynamic smem: As 2*16*256 floats (swizzled), Bs 2*16*256 floats (dup pairs)
#define SGEMM_SMEM ((2 * BK * BM) * 4 + (2 * BK * 2 * BN) * 4)   // 65536 B

typedef unsigned long long ull;

__device__ __forceinline__ ull pk2(float x, float y) {
    ull r; asm("mov.b64 %0, {%1, %2};" : "=l"(r) : "f"(x), "f"(y)); return r;
}
__device__ __forceinline__ void fma2(ull& c, ull a, ull b) {
    asm("fma.rn.f32x2 %0, %1, %2, %0;" : "+l"(c) : "l"(a), "l"(b));
}
__device__ __forceinline__ float2 up2(ull v) {
    float2 r; asm("mov.b64 {%0, %1}, %2;" : "=f"(r.x), "=f"(r.y) : "l"(v)); return r;
}

// ---------------------------------------------------------------------------
// Scratch
// ---------------------------------------------------------------------------
__device__ __align__(16) float g_h1  [(size_t)NT * DD];
__device__ __align__(16) float g_q   [(size_t)NT * DD];
__device__ __align__(16) float g_k   [(size_t)NT * KVD];
__device__ __align__(16) float g_v   [(size_t)NT * KVD];
__device__ __align__(16) float g_ctx [(size_t)NT * DD];
__device__ __align__(16) float g_attn[(size_t)NT * DD];
__device__ __align__(16) float g_res2[(size_t)NT * DD];
__device__ __align__(16) float g_flat[(size_t)NT * DD];
__device__ __align__(16) float g_G   [(size_t)NEXP * NT * FF];
__device__ __align__(16) float g_U   [(size_t)NEXP * NT * FF];
__device__ __align__(16) float g_O   [(size_t)NEXP * NT * DD];
__device__ int   g_cnt [NEXP];
__device__ int   g_list[NEXP * NT];
__device__ int   g_tok_e[NT * 2];
__device__ int   g_tok_i[NT * 2];
__device__ float g_tok_w[NT * 2];
__device__ float g_invf[32];

// ---------------------------------------------------------------------------
__global__ void k_zero_init() {
    int i = threadIdx.x;
    if (i < NEXP) g_cnt[i] = 0;
    if (i < 32) {
        double ex = -((double)(2 * i) / 64.0) * 13.28771237954944939; // log2(1e4)
        g_invf[i] = (float)exp2(ex);
    }
}

// ---------------------------------------------------------------------------
// RMSNorm 1
// ---------------------------------------------------------------------------
__global__ void __launch_bounds__(256) k_rms1(const float* __restrict__ x,
                                              const float* __restrict__ w) {
    int t = blockIdx.x, i = threadIdx.x;
    float4 v = ((const float4*)(x + (size_t)t * DD))[i];
    float ss = v.x * v.x + v.y * v.y + v.z * v.z + v.w * v.w;
    __shared__ float red[8];
    int lane = i & 31, wp = i >> 5;
    #pragma unroll
    for (int o = 16; o; o >>= 1) ss += __shfl_xor_sync(0xffffffffu, ss, o);
    if (!lane) red[wp] = ss;
    __syncthreads();
    if (i == 0) { float s = 0.f; for (int j = 0; j < 8; j++) s += red[j]; red[0] = s; }
    __syncthreads();
    float rs = rsqrtf(red[0] * (1.0f / DD) + EPS_RMS);
    float4 wv = ((const float4*)w)[i];
    ((float4*)(g_h1 + (size_t)t * DD))[i] =
        make_float4(v.x * rs * wv.x, v.y * rs * wv.y, v.z * rs * wv.z, v.w * rs * wv.w);
}

// ---------------------------------------------------------------------------
// SGEMM core: 256x128x16, 256 threads, 16Mx8N/thread, packed FFMA2.
// Conflict-free smem: A M-contiguous with XOR-chunk swizzle (folds to
// immediates), B g-interleaved duplicated (b,b) pairs, phase-contiguous dup
// stores. Inner loop: 8x LDS.128 + 64x FFMA2 per kk, zero packs.
// ---------------------------------------------------------------------------
__device__ __forceinline__ void sgemm_core(
    const float* a0, const float* a1, const float* a2r, const float* a3,
    const float* __restrict__ B, int ldb, int bcol,
    float* __restrict__ C, int ldc, int ccol,
    int Kd, int Me, int m0)
{
    extern __shared__ float smf[];
    float* As = smf;                   // [2][16][256] swizzled chunks
    float* Bs = smf + 2 * BK * BM;     // [2][16][256] dup pairs, g-interleaved

    int tid = threadIdx.x;
    int ar = tid >> 2, ac4 = tid & 3;          // A loader
    int arh = ar >> 2, arl = ar & 3;
    int whi = tid >> 6;                        // B loader k-row offset
    int wlo = tid & 63;
    int bg = wlo >> 4, btx = wlo & 15;         // B col pair base
    int bc0 = bcol + bg * 32 + btx * 2;
    int tr = tid >> 4, tx = tid & 15;          // compute mapping

    const float* ap[4] = {a0, a1, a2r, a3};

    ull acc[8][8];
    #pragma unroll
    for (int i = 0; i < 8; i++)
        #pragma unroll
        for (int j = 0; j < 8; j++) acc[i][j] = 0ull;

    int nk = Kd / BK;
    float4 va[4];
    float2 vb[4];

    // ---- prologue: tile 0 ----
    #pragma unroll
    for (int q = 0; q < 4; q++) va[q] = *(const float4*)(ap[q] + ac4 * 4);
    #pragma unroll
    for (int p = 0; p < 4; p++)
        vb[p] = *(const float2*)(B + (size_t)(p * 4 + whi) * ldb + bc0);
    #pragma unroll
    for (int q = 0; q < 4; q++) {
        float vals[4] = {va[q].x, va[q].y, va[q].z, va[q].w};
        int cb = arh + 16 * q;
        #pragma unroll
        for (int c = 0; c < 4; c++)
            As[(ac4 * 4 + c) * BM + ((cb ^ ac4) << 2) + arl] = vals[c];
    }
    #pragma unroll
    for (int p = 0; p < 4; p++)
        *(float4*)&Bs[p * 1024 + tid * 4] = make_float4(vb[p].x, vb[p].x, vb[p].y, vb[p].y);
    __syncthreads();

    for (int kt = 0; kt < nk; kt++) {
        if (kt + 1 < nk) {
            int kn = (kt + 1) * BK;
            #pragma unroll
            for (int q = 0; q < 4; q++) va[q] = *(const float4*)(ap[q] + kn + ac4 * 4);
            #pragma unroll
            for (int p = 0; p < 4; p++)
                vb[p] = *(const float2*)(B + (size_t)(kn + p * 4 + whi) * ldb + bc0);
        }
        int st = kt & 1;
        const float* Asb = As + st * (BK * BM) + tr * 16;
        const float* Bsb = Bs + st * (BK * 2 * BN) + tx * 4;
        #pragma unroll
        for (int kk = 0; kk < BK; kk++) {
            ull av[8], bd[8];
            int xk = kk >> 2;
            *(float4*)&av[0] = *(const float4*)&Asb[kk * BM + ((0 ^ xk) << 2)];
            *(float4*)&av[2] = *(const float4*)&Asb[kk * BM + ((1 ^ xk) << 2)];
            *(float4*)&av[4] = *(const float4*)&Asb[kk * BM + ((2 ^ xk) << 2)];
            *(float4*)&av[6] = *(const float4*)&Asb[kk * BM + ((3 ^ xk) << 2)];
            *(float4*)&bd[0] = *(const float4*)&Bsb[kk * 256 + 0 * 64];
            *(float4*)&bd[2] = *(const float4*)&Bsb[kk * 256 + 1 * 64];
            *(float4*)&bd[4] = *(const float4*)&Bsb[kk * 256 + 2 * 64];
            *(float4*)&bd[6] = *(const float4*)&Bsb[kk * 256 + 3 * 64];
            #pragma unroll
            for (int i = 0; i < 8; i++)
                #pragma unroll
                for (int j = 0; j < 8; j++)
                    fma2(acc[i][j], av[i], bd[j]);
        }
        if (kt + 1 < nk) {
            int s2 = (kt + 1) & 1;
            float* Asn = As + s2 * (BK * BM);
            float* Bsn = Bs + s2 * (BK * 2 * BN);
            #pragma unroll
            for (int q = 0; q < 4; q++) {
                float vals[4] = {va[q].x, va[q].y, va[q].z, va[q].w};
                int cb = arh + 16 * q;
                #pragma unroll
                for (int c = 0; c < 4; c++)
                    Asn[(ac4 * 4 + c) * BM + ((cb ^ ac4) << 2) + arl] = vals[c];
            }
            #pragma unroll
            for (int p = 0; p < 4; p++)
                *(float4*)&Bsn[p * 1024 + tid * 4] = make_float4(vb[p].x, vb[p].x, vb[p].y, vb[p].y);
        }
        __syncthreads();
    }

    // epilogue: acc[i][2g+r] -> row m0+tr*16+2i(+1), col ccol + g*32 + tx*2 + r
    #pragma unroll
    for (int i = 0; i < 8; i++) {
        int r0 = m0 + tr * 16 + 2 * i;
        #pragma unroll
        for (int g = 0; g < 4; g++) {
            float2 u0 = up2(acc[i][2 * g]);
            float2 u1 = up2(acc[i][2 * g + 1]);
            int col = ccol + g * 32 + tx * 2;
            if (r0 < Me)
                *(float2*)&C[(size_t)r0 * ldc + col] = make_float2(u0.x, u1.x);
            if (r0 + 1 < Me)
                *(float2*)&C[(size_t)(r0 + 1) * ldc + col] = make_float2(u0.y, u1.y);
        }
    }
}

// General SGEMM (expert batch + gather + runtime M)
__global__ void __launch_bounds__(256, 1) k_sgemm(
    const float* __restrict__ A, const float* __restrict__ B, float* __restrict__ C,
    int M, int N, int Kd,
    const int* __restrict__ rowlist, const int* __restrict__ counts,
    size_t strideAe, size_t strideBe, size_t strideCe)
{
    int e  = blockIdx.z;
    int Me = counts ? counts[e] : M;
    int m0 = blockIdx.y * BM;
    if (m0 >= Me) return;
    int n0 = blockIdx.x * BN;
    const float* Ab = A + (size_t)e * strideAe;
    const float* Bb = B + (size_t)e * strideBe;
    float*       Cb = C + (size_t)e * strideCe;

    int ar = threadIdx.x >> 2;
    const int* lst = rowlist ? (rowlist + e * NT) : (const int*)0;
    const float* ap[4];
    #pragma unroll
    for (int q = 0; q < 4; q++) {
        int r = m0 + ar + 64 * q; if (r > Me - 1) r = Me - 1;
        size_t gr = lst ? (size_t)lst[r] : (size_t)r;
        ap[q] = Ab + gr * (size_t)Kd;
    }
    sgemm_core(ap[0], ap[1], ap[2], ap[3], Bb, N, n0, Cb, N, n0, Kd, Me, m0);
}

// Fused QKV projection
__global__ void __launch_bounds__(256, 1) k_sgemm_qkv(
    const float* __restrict__ h1,
    const float* __restrict__ Wq, const float* __restrict__ Wk,
    const float* __restrict__ Wv)
{
    int bx = blockIdx.x;
    int m0 = blockIdx.y * BM;
    const float* B; float* C; int ldb, bcol;
    if (bx < 8)       { B = Wq; C = g_q; ldb = 1024; bcol = bx * 128; }
    else if (bx < 10) { B = Wk; C = g_k; ldb = KVD;  bcol = (bx - 8) * 128; }
    else              { B = Wv; C = g_v; ldb = KVD;  bcol = (bx - 10) * 128; }
    int ar = threadIdx.x >> 2;
    const float* ap[4];
    #pragma unroll
    for (int q = 0; q < 4; q++) ap[q] = h1 + (size_t)(m0 + ar + 64 * q) * DD;
    sgemm_core(ap[0], ap[1], ap[2], ap[3], B, ldb, bcol, C, ldb, bcol, DD, NT, m0);
}

// ---------------------------------------------------------------------------
// RoPE
// ---------------------------------------------------------------------------
__global__ void __launch_bounds__(512) k_rope_q() {
    int t = blockIdx.x;
    int h = threadIdx.x >> 5, i = threadIdx.x & 31;
    int pos = t & (SS - 1);
    float ang = (float)pos * g_invf[i];
    float s, c; sincosf(ang, &s, &c);
    size_t base = (size_t)t * DD + h * DH + i;
    float x1 = g_q[base], x2 = g_q[base + 32];
    g_q[base] = x1 * c - x2 * s;
    g_q[base + 32] = x2 * c + x1 * s;
}
__global__ void __launch_bounds__(128) k_rope_k() {
    int t = blockIdx.x;
    int h = threadIdx.x >> 5, i = threadIdx.x & 31;
    int pos = t & (SS - 1);
    float ang = (float)pos * g_invf[i];
    float s, c; sincosf(ang, &s, &c);
    size_t base = (size_t)t * KVD + h * DH + i;
    float x1 = g_k[base], x2 = g_k[base + 32];
    g_k[base] = x1 * c - x2 * s;
    g_k[base + 32] = x2 * c + x1 * s;
}

// ---------------------------------------------------------------------------
// Causal GQA flash attention with packed FFMA2 dot/pv loops.
// ---------------------------------------------------------------------------
__global__ void __launch_bounds__(128) k_attn() {
    int qt = blockIdx.x;
    int bh = blockIdx.y;
    int b = bh >> 4, h = bh & 15, hk = h >> 2;
    int tid = threadIdx.x;
    extern __shared__ float sm[];
    float* Ks = sm;
    float* Vs = sm + 4096;
    float* Sr = sm + 8192;

    int qi = qt * 128 + tid;
    int t  = b * SS + qi;
    float2 q2[32];
    {
        const float4* qp = (const float4*)(g_q + (size_t)t * DD + h * DH);
        #pragma unroll
        for (int u = 0; u < 16; u++) {
            float4 x = qp[u];
            q2[2 * u]     = make_float2(x.x * 0.125f, x.y * 0.125f);
            q2[2 * u + 1] = make_float2(x.z * 0.125f, x.w * 0.125f);
        }
    }
    float2 a2[32];
    #pragma unroll
    for (int d = 0; d < 32; d++) a2[d] = make_float2(0.f, 0.f);
    float m = -3e38f, l = 0.f;

    int jmax = 2 * qt + 1;
    for (int jt = 0; jt <= jmax; jt++) {
        int kb = b * SS + jt * 64;
        #pragma unroll
        for (int u = 0; u < 8; u++) {
            int lin = u * 128 + tid;
            int row = lin >> 4, c4 = lin & 15;
            *(float4*)(Ks + row * 64 + c4 * 4) =
                *(const float4*)(g_k + (size_t)(kb + row) * KVD + hk * DH + c4 * 4);
            *(float4*)(Vs + row * 64 + c4 * 4) =
                *(const float4*)(g_v + (size_t)(kb + row) * KVD + hk * DH + c4 * 4);
        }
        __syncthreads();
        int lim = qi - jt * 64;
        if (lim >= 0) {
            int cmax = lim < 63 ? lim : 63;
            float smax = -3e38f;
            for (int c = 0; c <= cmax; c++) {
                const float4* kr = (const float4*)(Ks + c * 64);
                ull s2 = 0ull;
                #pragma unroll
                for (int d4 = 0; d4 < 16; d4++) {
                    float4 kv = kr[d4];
                    fma2(s2, *(ull*)&q2[2 * d4],     *(ull*)&kv.x);
                    fma2(s2, *(ull*)&q2[2 * d4 + 1], *(ull*)&kv.z);
                }
                float2 sr = up2(s2);
                float s = sr.x + sr.y;
                Sr[tid * 65 + c] = s;
                smax = fmaxf(smax, s);
            }
            float mnew = fmaxf(m, smax);
            float corr = __expf(m - mnew);
            l *= corr;
            #pragma unroll
            for (int d = 0; d < 32; d++) { a2[d].x *= corr; a2[d].y *= corr; }
            for (int c = 0; c <= cmax; c++) {
                float p = __expf(Sr[tid * 65 + c] - mnew);
                l += p;
                ull pd = pk2(p, p);
                const float4* vr = (const float4*)(Vs + c * 64);
                #pragma unroll
                for (int d4 = 0; d4 < 16; d4++) {
                    float4 vv = vr[d4];
                    fma2(*(ull*)&a2[2 * d4],     *(ull*)&vv.x, pd);
                    fma2(*(ull*)&a2[2 * d4 + 1], *(ull*)&vv.z, pd);
                }
            }
            m = mnew;
        }
        __syncthreads();
    }
    float inv = 1.0f / l;
    float4* op = (float4*)(g_ctx + (size_t)t * DD + h * DH);
    #pragma unroll
    for (int u = 0; u < 16; u++)
        op[u] = make_float4(a2[2 * u].x * inv, a2[2 * u].y * inv,
                            a2[2 * u + 1].x * inv, a2[2 * u + 1].y * inv);
}

// ---------------------------------------------------------------------------
// residual add + clip + RMSNorm2
// ---------------------------------------------------------------------------
__global__ void __launch_bounds__(256) k_post(const float* __restrict__ hidden,
                                              const float* __restrict__ w2) {
    int t = blockIdx.x, i = threadIdx.x;
    float4 hv = ((const float4*)(hidden + (size_t)t * DD))[i];
    float4 av = ((const float4*)(g_attn + (size_t)t * DD))[i];
    float4 s;
    s.x = fminf(fmaxf(hv.x + av.x, -100.f), 100.f);
    s.y = fminf(fmaxf(hv.y + av.y, -100.f), 100.f);
    s.z = fminf(fmaxf(hv.z + av.z, -100.f), 100.f);
    s.w = fminf(fmaxf(hv.w + av.w, -100.f), 100.f);
    ((float4*)(g_res2 + (size_t)t * DD))[i] = s;
    float ss = s.x * s.x + s.y * s.y + s.z * s.z + s.w * s.w;
    __shared__ float red[8];
    int lane = i & 31, wp = i >> 5;
    #pragma unroll
    for (int o = 16; o; o >>= 1) ss += __shfl_xor_sync(0xffffffffu, ss, o);
    if (!lane) red[wp] = ss;
    __syncthreads();
    if (i == 0) { float z = 0.f; for (int j = 0; j < 8; j++) z += red[j]; red[0] = z; }
    __syncthreads();
    float rs = rsqrtf(red[0] * (1.0f / DD) + EPS_RMS);
    float4 wv = ((const float4*)w2)[i];
    ((float4*)(g_flat + (size_t)t * DD))[i] =
        make_float4(s.x * rs * wv.x, s.y * rs * wv.y, s.z * rs * wv.z, s.w * rs * wv.w);
}

// ---------------------------------------------------------------------------
// Router
// ---------------------------------------------------------------------------
__global__ void __launch_bounds__(256) k_router(const float* __restrict__ Wr) {
    int t = blockIdx.x;
    int lane = threadIdx.x & 31, w = threadIdx.x >> 5;
    const float* fr = g_flat + (size_t)t * DD;
    float s = 0.f;
    for (int d = lane; d < DD; d += 32) s += fr[d] * Wr[d * NEXP + w];
    #pragma unroll
    for (int o = 16; o; o >>= 1) s += __shfl_xor_sync(0xffffffffu, s, o);
    __shared__ float lg[NEXP];
    if (!lane) lg[w] = s;
    __syncthreads();
    if (threadIdx.x == 0) {
        float l0 = -3e38f; int i0 = 0;
        #pragma unroll
        for (int e2 = 0; e2 < NEXP; e2++) if (lg[e2] > l0) { l0 = lg[e2]; i0 = e2; }
        float l1 = -3e38f; int i1 = 0;
        #pragma unroll
        for (int e2 = 0; e2 < NEXP; e2++)
            if (e2 != i0 && lg[e2] > l1) { l1 = lg[e2]; i1 = e2; }
        float p1 = __expf(l1 - l0);
        float w0 = 1.0f / (1.0f + p1), w1 = p1 / (1.0f + p1);
        int pos0 = atomicAdd(&g_cnt[i0], 1);
        g_list[i0 * NT + pos0] = t;
        g_tok_e[t * 2] = i0; g_tok_i[t * 2] = pos0; g_tok_w[t * 2] = w0;
        int pos1 = atomicAdd(&g_cnt[i1], 1);
        g_list[i1 * NT + pos1] = t;
        g_tok_e[t * 2 + 1] = i1; g_tok_i[t * 2 + 1] = pos1; g_tok_w[t * 2 + 1] = w1;
    }
}

// ---------------------------------------------------------------------------
// SiLU(g)*u in place into g_G
// ---------------------------------------------------------------------------
__global__ void __launch_bounds__(256) k_act() {
    int e = blockIdx.y, r = blockIdx.x;
    if (r >= g_cnt[e]) return;
    size_t base4 = (((size_t)e * NT + r) * FF) >> 2;
    float4* G4 = (float4*)g_G;
    const float4* U4 = (const float4*)g_U;
    for (int f = threadIdx.x; f < FF / 4; f += 256) {
        float4 g = G4[base4 + f], u = U4[base4 + f];
        g.x = g.x / (1.f + __expf(-g.x)) * u.x;
        g.y = g.y / (1.f + __expf(-g.y)) * u.y;
        g.z = g.z / (1.f + __expf(-g.z)) * u.z;
        g.w = g.w / (1.f + __expf(-g.w)) * u.w;
        G4[base4 + f] = g;
    }
}

// ---------------------------------------------------------------------------
// Final combine
// ---------------------------------------------------------------------------
__global__ void __launch_bounds__(256) k_combine(float* __restrict__ out) {
    int t = blockIdx.x, i = threadIdx.x;
    int e0 = g_tok_e[t * 2],     i0 = g_tok_i[t * 2];     float w0 = g_tok_w[t * 2];
    int e1 = g_tok_e[t * 2 + 1], i1 = g_tok_i[t * 2 + 1]; float w1 = g_tok_w[t * 2 + 1];
    const float4* o0 = (const float4*)(g_O + ((size_t)e0 * NT + i0) * DD);
    const float4* o1 = (const float4*)(g_O + ((size_t)e1 * NT + i1) * DD);
    const float4* rr = (const float4*)(g_res2 + (size_t)t * DD);
    float4 a = rr[i], x = o0[i], y = o1[i], o;
    o.x = fminf(fmaxf(a.x + w0 * x.x + w1 * y.x, -100.f), 100.f);
    o.y = fminf(fmaxf(a.y + w0 * x.y + w1 * y.y, -100.f), 100.f);
    o.z = fminf(fmaxf(a.z + w0 * x.z + w1 * y.z, -100.f), 100.f);
    o.w = fminf(fmaxf(a.w + w0 * x.w + w1 * y.w, -100.f), 100.f);
    ((float4*)(out + (size_t)t * DD))[i] = o;
}

// ---------------------------------------------------------------------------
// Host launcher
// ---------------------------------------------------------------------------
extern "C" void kernel_launch(void* const* d_in, const int* in_sizes, int n_in,
                              void* d_out, int out_size) {
    const float* hidden = (const float*)d_in[0];
    const float* ln1    = (const float*)d_in[1];
    const float* ln2    = (const float*)d_in[2];
    const float* Wq     = (const float*)d_in[3];
    const float* Wk     = (const float*)d_in[4];
    const float* Wv     = (const float*)d_in[5];
    const float* Wo     = (const float*)d_in[6];
    const float* Wr     = (const float*)d_in[7];
    const float* Wg     = (const float*)d_in[8];
    const float* Wu     = (const float*)d_in[9];
    const float* Wd     = (const float*)d_in[10];
    float* out = (float*)d_out;
    (void)in_sizes; (void)n_in; (void)out_size;

    float *p_h1, *p_ctx, *p_attn, *p_flat, *p_G, *p_U, *p_O;
    int *p_lst, *p_cnt;
    cudaGetSymbolAddress((void**)&p_h1,  g_h1);
    cudaGetSymbolAddress((void**)&p_ctx, g_ctx);
    cudaGetSymbolAddress((void**)&p_attn,g_attn);
    cudaGetSymbolAddress((void**)&p_flat,g_flat);
    cudaGetSymbolAddress((void**)&p_G,   g_G);
    cudaGetSymbolAddress((void**)&p_U,   g_U);
    cudaGetSymbolAddress((void**)&p_O,   g_O);
    cudaGetSymbolAddress((void**)&p_lst, g_list);
    cudaGetSymbolAddress((void**)&p_cnt, g_cnt);

    const int ATTN_SMEM = (4096 + 4096 + 128 * 65) * 4;   // 66048 B
    static int s_attr_done = 0;
    if (!s_attr_done) {
        cudaFuncSetAttribute(k_attn, cudaFuncAttributeMaxDynamicSharedMemorySize, ATTN_SMEM);
        cudaFuncSetAttribute(k_sgemm, cudaFuncAttributeMaxDynamicSharedMemorySize, SGEMM_SMEM);
        cudaFuncSetAttribute(k_sgemm_qkv, cudaFuncAttributeMaxDynamicSharedMemorySize, SGEMM_SMEM);
        s_attr_done = 1;
    }

    k_zero_init<<<1, 32>>>();
    k_rms1<<<NT, 256>>>(hidden, ln1);

    k_sgemm_qkv<<<dim3(12, NT / BM), 256, SGEMM_SMEM>>>(p_h1, Wq, Wk, Wv);

    k_rope_q<<<NT, 512>>>();
    k_rope_k<<<NT, 128>>>();

    k_attn<<<dim3(16, 32), 128, ATTN_SMEM>>>();

    k_sgemm<<<dim3(8, NT / BM, 1), 256, SGEMM_SMEM>>>((const float*)p_ctx, Wo, p_attn,
                                          NT, 1024, 1024, 0, 0, 0, 0, 0);

    k_post<<<NT, 256>>>(hidden, ln2);
    k_router<<<NT, 256>>>(Wr);

    k_sgemm<<<dim3(16, NT / BM, NEXP), 256, SGEMM_SMEM>>>((const float*)p_flat, Wg, p_G, 0, FF, DD,
                                              p_lst, p_cnt, 0, (size_t)DD * FF, (size_t)NT * FF);
    k_sgemm<<<dim3(16, NT / BM, NEXP), 256, SGEMM_SMEM>>>((const float*)p_flat, Wu, p_U, 0, FF, DD,
                                              p_lst, p_cnt, 0, (size_t)DD * FF, (size_t)NT * FF);
    k_act<<<dim3(NT, NEXP), 256>>>();
    k_sgemm<<<dim3(8, NT / BM, NEXP), 256, SGEMM_SMEM>>>((const float*)p_G, Wd, p_O, 0, DD, FF,
                                             0, p_cnt, (size_t)NT * FF, (size_t)FF * DD, (size_t)NT * DD);

    k_combine<<<NT, 256>>>(out);
}

// round 11
// speedup vs baseline: 2.0693x; 1.3929x over previous
#include <cuda_runtime.h>
#include <cuda_bf16.h>
#include <math.h>
#include <stdint.h>

// Problem constants
#define NT   4096
#define DD   1024
#define SS   2048
#define NHQ  16
#define NHKV 4
#define DH   64
#define KVD  (NHKV * DH)   // 256
#define FF   2048
#define NEXP 8
#define EPS_RMS 1e-5f

#define BM 256
#define BN 128
#define BK 16
#define SGEMM_SMEM ((2 * BK * BM) * 4 + (2 * BK * 2 * BN) * 4)   // 65536 B

typedef unsigned long long ull;
typedef __nv_bfloat16 bf16;

__device__ __forceinline__ ull pk2(float x, float y) {
    ull r; asm("mov.b64 %0, {%1, %2};" : "=l"(r) : "f"(x), "f"(y)); return r;
}
__device__ __forceinline__ void fma2(ull& c, ull a, ull b) {
    asm("fma.rn.f32x2 %0, %1, %2, %0;" : "+l"(c) : "l"(a), "l"(b));
}
__device__ __forceinline__ float2 up2(ull v) {
    float2 r; asm("mov.b64 {%0, %1}, %2;" : "=f"(r.x), "=f"(r.y) : "l"(v)); return r;
}
__device__ __forceinline__ uint32_t smem_u32(const void* p) {
    uint32_t a;
    asm("{ .reg .u64 t; cvta.to.shared.u64 t, %1; cvt.u32.u64 %0, t; }" : "=r"(a) : "l"(p));
    return a;
}
// warp-level tensor core primitives (sm_80+, valid on base sm_100)
__device__ __forceinline__ void ldm_x4(uint32_t r[4], uint32_t addr) {
    asm volatile("ldmatrix.sync.aligned.m8n8.x4.shared.b16 {%0,%1,%2,%3}, [%4];"
        : "=r"(r[0]), "=r"(r[1]), "=r"(r[2]), "=r"(r[3]) : "r"(addr));
}
__device__ __forceinline__ void mma16816(float c[4], const uint32_t a[4],
                                         uint32_t b0, uint32_t b1) {
    asm volatile("mma.sync.aligned.m16n8k16.row.col.f32.bf16.bf16.f32 "
        "{%0,%1,%2,%3}, {%4,%5,%6,%7}, {%8,%9}, {%0,%1,%2,%3};"
        : "+f"(c[0]), "+f"(c[1]), "+f"(c[2]), "+f"(c[3])
        : "r"(a[0]), "r"(a[1]), "r"(a[2]), "r"(a[3]), "r"(b0), "r"(b1));
}
__device__ __forceinline__ void split_bf(float x, bf16& h, bf16& l) {
    h = __float2bfloat16(x);
    l = __float2bfloat16(x - __bfloat162float(h));
}
__device__ __forceinline__ ushort4 pack4(bf16 a, bf16 b, bf16 c, bf16 d) {
    ushort4 s;
    s.x = __bfloat16_as_ushort(a); s.y = __bfloat16_as_ushort(b);
    s.z = __bfloat16_as_ushort(c); s.w = __bfloat16_as_ushort(d);
    return s;
}

// ---------------------------------------------------------------------------
// Scratch
// ---------------------------------------------------------------------------
__device__ __align__(16) float g_h1  [(size_t)NT * DD];
__device__ __align__(16) float g_q   [(size_t)NT * DD];
__device__ __align__(16) float g_k   [(size_t)NT * KVD];
__device__ __align__(16) float g_v   [(size_t)NT * KVD];
__device__ __align__(16) float g_ctx [(size_t)NT * DD];
__device__ __align__(16) float g_attn[(size_t)NT * DD];
__device__ __align__(16) float g_res2[(size_t)NT * DD];
__device__ __align__(16) float g_flat[(size_t)NT * DD];
__device__ __align__(16) float g_G   [(size_t)NEXP * NT * FF];
__device__ __align__(16) float g_U   [(size_t)NEXP * NT * FF];
__device__ __align__(16) float g_O   [(size_t)NEXP * NT * DD];
__device__ int   g_cnt [NEXP];
__device__ int   g_list[NEXP * NT];
__device__ int   g_tok_e[NT * 2];
__device__ int   g_tok_i[NT * 2];
__device__ float g_tok_w[NT * 2];
__device__ float g_invf[32];

// bf16 split buffers
__device__ __align__(16) bf16 g_flat_hi[(size_t)NT * DD];
__device__ __align__(16) bf16 g_flat_lo[(size_t)NT * DD];
__device__ __align__(16) bf16 g_act_hi[(size_t)NEXP * NT * FF];
__device__ __align__(16) bf16 g_act_lo[(size_t)NEXP * NT * FF];
__device__ __align__(16) bf16 g_wgT_hi[(size_t)NEXP * FF * DD];
__device__ __align__(16) bf16 g_wgT_lo[(size_t)NEXP * FF * DD];
__device__ __align__(16) bf16 g_wuT_hi[(size_t)NEXP * FF * DD];
__device__ __align__(16) bf16 g_wuT_lo[(size_t)NEXP * FF * DD];
__device__ __align__(16) bf16 g_wdT_hi[(size_t)NEXP * DD * FF];
__device__ __align__(16) bf16 g_wdT_lo[(size_t)NEXP * DD * FF];

// ---------------------------------------------------------------------------
__global__ void k_zero_init() {
    int i = threadIdx.x;
    if (i < NEXP) g_cnt[i] = 0;
    if (i < 32) {
        double ex = -((double)(2 * i) / 64.0) * 13.28771237954944939;
        g_invf[i] = (float)exp2(ex);
    }
}

// ---------------------------------------------------------------------------
// Weight transpose + bf16 hi/lo split: W[K][N] -> T[N][K]
// ---------------------------------------------------------------------------
__global__ void __launch_bounds__(256) k_wt(const float* __restrict__ W,
                                            bf16* __restrict__ Thi, bf16* __restrict__ Tlo,
                                            int Kd, int N, size_t wstride, size_t tstride) {
    int e = blockIdx.z;
    const float* Wb = W + (size_t)e * wstride;
    bf16* th = Thi + (size_t)e * tstride;
    bf16* tl = Tlo + (size_t)e * tstride;
    __shared__ float t[32][33];
    int kb = blockIdx.y * 32, nb = blockIdx.x * 32;
    int tx = threadIdx.x & 31, ty = threadIdx.x >> 5;
    #pragma unroll
    for (int j = 0; j < 4; j++)
        t[ty + j * 8][tx] = Wb[(size_t)(kb + ty + j * 8) * N + nb + tx];
    __syncthreads();
    #pragma unroll
    for (int j = 0; j < 4; j++) {
        int n = ty + j * 8;
        float x = t[tx][n];
        bf16 h, l; split_bf(x, h, l);
        th[(size_t)(nb + n) * Kd + kb + tx] = h;
        tl[(size_t)(nb + n) * Kd + kb + tx] = l;
    }
}

// ---------------------------------------------------------------------------
// RMSNorm 1 -> g_h1
// ---------------------------------------------------------------------------
__global__ void __launch_bounds__(256) k_rms1(const float* __restrict__ x,
                                              const float* __restrict__ w) {
    int t = blockIdx.x, i = threadIdx.x;
    float4 v = ((const float4*)(x + (size_t)t * DD))[i];
    float ss = v.x * v.x + v.y * v.y + v.z * v.z + v.w * v.w;
    __shared__ float red[8];
    int lane = i & 31, wp = i >> 5;
    #pragma unroll
    for (int o = 16; o; o >>= 1) ss += __shfl_xor_sync(0xffffffffu, ss, o);
    if (!lane) red[wp] = ss;
    __syncthreads();
    if (i == 0) { float s = 0.f; for (int j = 0; j < 8; j++) s += red[j]; red[0] = s; }
    __syncthreads();
    float rs = rsqrtf(red[0] * (1.0f / DD) + EPS_RMS);
    float4 wv = ((const float4*)w)[i];
    ((float4*)(g_h1 + (size_t)t * DD))[i] =
        make_float4(v.x * rs * wv.x, v.y * rs * wv.y, v.z * rs * wv.z, v.w * rs * wv.w);
}

// ---------------------------------------------------------------------------
// FFMA2 SGEMM (QKV / Wo — exact fp32 path feeding the router)
// ---------------------------------------------------------------------------
__device__ __forceinline__ void sgemm_core(
    const float* a0, const float* a1, const float* a2r, const float* a3,
    const float* __restrict__ B, int ldb, int bcol,
    float* __restrict__ C, int ldc, int ccol,
    int Kd, int Me, int m0)
{
    extern __shared__ float smf[];
    float* As = smf;
    float* Bs = smf + 2 * BK * BM;

    int tid = threadIdx.x;
    int ar = tid >> 2, ac4 = tid & 3;
    int arh = ar >> 2, arl = ar & 3;
    int whi = tid >> 6;
    int wlo = tid & 63;
    int bg = wlo >> 4, btx = wlo & 15;
    int bc0 = bcol + bg * 32 + btx * 2;
    int tr = tid >> 4, tx = tid & 15;

    const float* ap[4] = {a0, a1, a2r, a3};
    ull acc[8][8];
    #pragma unroll
    for (int i = 0; i < 8; i++)
        #pragma unroll
        for (int j = 0; j < 8; j++) acc[i][j] = 0ull;

    int nk = Kd / BK;
    float4 va[4];
    float2 vb[4];

    #pragma unroll
    for (int q = 0; q < 4; q++) va[q] = *(const float4*)(ap[q] + ac4 * 4);
    #pragma unroll
    for (int p = 0; p < 4; p++)
        vb[p] = *(const float2*)(B + (size_t)(p * 4 + whi) * ldb + bc0);
    #pragma unroll
    for (int q = 0; q < 4; q++) {
        float vals[4] = {va[q].x, va[q].y, va[q].z, va[q].w};
        int cb = arh + 16 * q;
        #pragma unroll
        for (int c = 0; c < 4; c++)
            As[(ac4 * 4 + c) * BM + ((cb ^ ac4) << 2) + arl] = vals[c];
    }
    #pragma unroll
    for (int p = 0; p < 4; p++)
        *(float4*)&Bs[p * 1024 + tid * 4] = make_float4(vb[p].x, vb[p].x, vb[p].y, vb[p].y);
    __syncthreads();

    for (int kt = 0; kt < nk; kt++) {
        if (kt + 1 < nk) {
            int kn = (kt + 1) * BK;
            #pragma unroll
            for (int q = 0; q < 4; q++) va[q] = *(const float4*)(ap[q] + kn + ac4 * 4);
            #pragma unroll
            for (int p = 0; p < 4; p++)
                vb[p] = *(const float2*)(B + (size_t)(kn + p * 4 + whi) * ldb + bc0);
        }
        int st = kt & 1;
        const float* Asb = As + st * (BK * BM) + tr * 16;
        const float* Bsb = Bs + st * (BK * 2 * BN) + tx * 4;
        #pragma unroll
        for (int kk = 0; kk < BK; kk++) {
            ull av[8], bd[8];
            int xk = kk >> 2;
            *(float4*)&av[0] = *(const float4*)&Asb[kk * BM + ((0 ^ xk) << 2)];
            *(float4*)&av[2] = *(const float4*)&Asb[kk * BM + ((1 ^ xk) << 2)];
            *(float4*)&av[4] = *(const float4*)&Asb[kk * BM + ((2 ^ xk) << 2)];
            *(float4*)&av[6] = *(const float4*)&Asb[kk * BM + ((3 ^ xk) << 2)];
            *(float4*)&bd[0] = *(const float4*)&Bsb[kk * 256 + 0 * 64];
            *(float4*)&bd[2] = *(const float4*)&Bsb[kk * 256 + 1 * 64];
            *(float4*)&bd[4] = *(const float4*)&Bsb[kk * 256 + 2 * 64];
            *(float4*)&bd[6] = *(const float4*)&Bsb[kk * 256 + 3 * 64];
            #pragma unroll
            for (int i = 0; i < 8; i++)
                #pragma unroll
                for (int j = 0; j < 8; j++)
                    fma2(acc[i][j], av[i], bd[j]);
        }
        if (kt + 1 < nk) {
            int s2 = (kt + 1) & 1;
            float* Asn = As + s2 * (BK * BM);
            float* Bsn = Bs + s2 * (BK * 2 * BN);
            #pragma unroll
            for (int q = 0; q < 4; q++) {
                float vals[4] = {va[q].x, va[q].y, va[q].z, va[q].w};
                int cb = arh + 16 * q;
                #pragma unroll
                for (int c = 0; c < 4; c++)
                    Asn[(ac4 * 4 + c) * BM + ((cb ^ ac4) << 2) + arl] = vals[c];
            }
            #pragma unroll
            for (int p = 0; p < 4; p++)
                *(float4*)&Bsn[p * 1024 + tid * 4] = make_float4(vb[p].x, vb[p].x, vb[p].y, vb[p].y);
        }
        __syncthreads();
    }

    #pragma unroll
    for (int i = 0; i < 8; i++) {
        int r0 = m0 + tr * 16 + 2 * i;
        #pragma unroll
        for (int g = 0; g < 4; g++) {
            float2 u0 = up2(acc[i][2 * g]);
            float2 u1 = up2(acc[i][2 * g + 1]);
            int col = ccol + g * 32 + tx * 2;
            if (r0 < Me)
                *(float2*)&C[(size_t)r0 * ldc + col] = make_float2(u0.x, u1.x);
            if (r0 + 1 < Me)
                *(float2*)&C[(size_t)(r0 + 1) * ldc + col] = make_float2(u0.y, u1.y);
        }
    }
}

__global__ void __launch_bounds__(256, 1) k_sgemm(
    const float* __restrict__ A, const float* __restrict__ B, float* __restrict__ C,
    int M, int N, int Kd)
{
    int m0 = blockIdx.y * BM;
    int n0 = blockIdx.x * BN;
    int ar = threadIdx.x >> 2;
    const float* ap[4];
    #pragma unroll
    for (int q = 0; q < 4; q++) {
        int r = m0 + ar + 64 * q; if (r > M - 1) r = M - 1;
        ap[q] = A + (size_t)r * Kd;
    }
    sgemm_core(ap[0], ap[1], ap[2], ap[3], B, N, n0, C, N, n0, Kd, M, m0);
}

__global__ void __launch_bounds__(256, 1) k_sgemm_qkv(
    const float* __restrict__ h1,
    const float* __restrict__ Wq, const float* __restrict__ Wk,
    const float* __restrict__ Wv)
{
    int bx = blockIdx.x;
    int m0 = blockIdx.y * BM;
    const float* B; float* C; int ldb, bcol;
    if (bx < 8)       { B = Wq; C = g_q; ldb = 1024; bcol = bx * 128; }
    else if (bx < 10) { B = Wk; C = g_k; ldb = KVD;  bcol = (bx - 8) * 128; }
    else              { B = Wv; C = g_v; ldb = KVD;  bcol = (bx - 10) * 128; }
    int ar = threadIdx.x >> 2;
    const float* ap[4];
    #pragma unroll
    for (int q = 0; q < 4; q++) ap[q] = h1 + (size_t)(m0 + ar + 64 * q) * DD;
    sgemm_core(ap[0], ap[1], ap[2], ap[3], B, ldb, bcol, C, ldb, bcol, DD, NT, m0);
}

// ---------------------------------------------------------------------------
// MoE GEMM on warp-level tensor cores (mma.sync m16n8k16 bf16, base sm_100 OK).
// C[128x128]/CTA = (Ahi+Alo) @ (Bhi+Blo)^T via 3 products (hh, hl, lh).
// A [M][K] bf16 hi/lo (row gather); BT [N][K] bf16 hi/lo. fp32 accum in regs.
// 8 warps in 2x4 grid, warp tile 64x32, K-chunk 32, smem rows padded to 40.
// ---------------------------------------------------------------------------
#define LDP 40   // padded row length (elements); 80B stride -> conflict-free ldmatrix
__global__ void __launch_bounds__(256, 1) k_mma_gemm(
    const bf16* __restrict__ Ahi, const bf16* __restrict__ Alo, int lda, size_t sAe,
    const bf16* __restrict__ Bhi, const bf16* __restrict__ Blo, size_t sBe,
    float* __restrict__ C, int ldc, size_t sCe,
    int M, int Kd,
    const int* __restrict__ rowlist, const int* __restrict__ counts)
{
    int e = blockIdx.z;
    int Me = counts ? counts[e] : M;
    int m0 = blockIdx.y * 128;
    if (m0 >= Me) return;
    int n0 = blockIdx.x * 128;

    __shared__ bf16 sAh[128 * LDP], sAl[128 * LDP];
    __shared__ bf16 sBh[128 * LDP], sBl[128 * LDP];

    int tid = threadIdx.x;
    int lane = tid & 31, wid = tid >> 5;
    int warp_m = wid >> 2, warp_n = wid & 3;    // 2 x 4 warp grid

    // ---- loader mapping: 2 rows per thread per matrix, 16B chunks ----
    int lrow0 = tid >> 2, lrow1 = lrow0 + 64, lch = tid & 3;
    int ra0 = m0 + lrow0; if (ra0 > Me - 1) ra0 = Me - 1;
    int ra1 = m0 + lrow1; if (ra1 > Me - 1) ra1 = Me - 1;
    size_t ga0 = rowlist ? (size_t)rowlist[e * NT + ra0] : (size_t)ra0;
    size_t ga1 = rowlist ? (size_t)rowlist[e * NT + ra1] : (size_t)ra1;
    const bf16* pa0h = Ahi + (size_t)e * sAe + ga0 * (size_t)lda;
    const bf16* pa0l = Alo + (size_t)e * sAe + ga0 * (size_t)lda;
    const bf16* pa1h = Ahi + (size_t)e * sAe + ga1 * (size_t)lda;
    const bf16* pa1l = Alo + (size_t)e * sAe + ga1 * (size_t)lda;
    const bf16* pb0h = Bhi + (size_t)e * sBe + (size_t)(n0 + lrow0) * Kd;
    const bf16* pb0l = Blo + (size_t)e * sBe + (size_t)(n0 + lrow0) * Kd;
    const bf16* pb1h = Bhi + (size_t)e * sBe + (size_t)(n0 + lrow1) * Kd;
    const bf16* pb1l = Blo + (size_t)e * sBe + (size_t)(n0 + lrow1) * Kd;

    // ---- ldmatrix per-lane address components ----
    int a_row = lane & 15;                           // + warp_m*64 + mi*16
    int a_col = (lane >> 4) * 8;                     // + ks*16
    int b_row = ((lane >> 4) * 8) + (lane & 7);      // + warp_n*32 + p*16
    int b_col = ((lane >> 3) & 1) * 8;               // + ks*16

    float acc[4][4][4];
    #pragma unroll
    for (int mi = 0; mi < 4; mi++)
        #pragma unroll
        for (int ni = 0; ni < 4; ni++)
            #pragma unroll
            for (int r = 0; r < 4; r++) acc[mi][ni][r] = 0.f;

    for (int kc = 0; kc < Kd; kc += 32) {
        // load 32-wide K slab of all 4 matrices
        *(uint4*)&sAh[lrow0 * LDP + lch * 8] = *(const uint4*)(pa0h + kc + lch * 8);
        *(uint4*)&sAh[lrow1 * LDP + lch * 8] = *(const uint4*)(pa1h + kc + lch * 8);
        *(uint4*)&sAl[lrow0 * LDP + lch * 8] = *(const uint4*)(pa0l + kc + lch * 8);
        *(uint4*)&sAl[lrow1 * LDP + lch * 8] = *(const uint4*)(pa1l + kc + lch * 8);
        *(uint4*)&sBh[lrow0 * LDP + lch * 8] = *(const uint4*)(pb0h + kc + lch * 8);
        *(uint4*)&sBh[lrow1 * LDP + lch * 8] = *(const uint4*)(pb1h + kc + lch * 8);
        *(uint4*)&sBl[lrow0 * LDP + lch * 8] = *(const uint4*)(pb0l + kc + lch * 8);
        *(uint4*)&sBl[lrow1 * LDP + lch * 8] = *(const uint4*)(pb1l + kc + lch * 8);
        __syncthreads();

        #pragma unroll
        for (int ks = 0; ks < 2; ks++) {
            int kof = ks * 16;
            uint32_t ah[4][4], al[4][4];
            #pragma unroll
            for (int mi = 0; mi < 4; mi++) {
                int r = warp_m * 64 + mi * 16 + a_row;
                ldm_x4(ah[mi], smem_u32(&sAh[r * LDP + kof + a_col]));
                ldm_x4(al[mi], smem_u32(&sAl[r * LDP + kof + a_col]));
            }
            uint32_t bh[2][4], bl[2][4];
            #pragma unroll
            for (int p = 0; p < 2; p++) {
                int r = warp_n * 32 + p * 16 + b_row;
                ldm_x4(bh[p], smem_u32(&sBh[r * LDP + kof + b_col]));
                ldm_x4(bl[p], smem_u32(&sBl[r * LDP + kof + b_col]));
            }
            #pragma unroll
            for (int mi = 0; mi < 4; mi++)
                #pragma unroll
                for (int ni = 0; ni < 4; ni++) {
                    int p = ni >> 1, o = (ni & 1) * 2;
                    mma16816(acc[mi][ni], ah[mi], bh[p][o], bh[p][o + 1]);
                    mma16816(acc[mi][ni], ah[mi], bl[p][o], bl[p][o + 1]);
                    mma16816(acc[mi][ni], al[mi], bh[p][o], bh[p][o + 1]);
                }
        }
        __syncthreads();
    }

    // epilogue: frag (mi,ni): rows m0+warp_m*64+mi*16+lane/4 (+8), cols +2*(lane%4)
    float* Cb = C + (size_t)e * sCe;
    #pragma unroll
    for (int mi = 0; mi < 4; mi++) {
        int r0 = m0 + warp_m * 64 + mi * 16 + (lane >> 2);
        #pragma unroll
        for (int ni = 0; ni < 4; ni++) {
            int cc = n0 + warp_n * 32 + ni * 8 + (lane & 3) * 2;
            if (r0 < Me)
                *(float2*)&Cb[(size_t)r0 * ldc + cc] = make_float2(acc[mi][ni][0], acc[mi][ni][1]);
            if (r0 + 8 < Me)
                *(float2*)&Cb[(size_t)(r0 + 8) * ldc + cc] = make_float2(acc[mi][ni][2], acc[mi][ni][3]);
        }
    }
}

// ---------------------------------------------------------------------------
// RoPE
// ---------------------------------------------------------------------------
__global__ void __launch_bounds__(512) k_rope_q() {
    int t = blockIdx.x;
    int h = threadIdx.x >> 5, i = threadIdx.x & 31;
    int pos = t & (SS - 1);
    float ang = (float)pos * g_invf[i];
    float s, c; sincosf(ang, &s, &c);
    size_t base = (size_t)t * DD + h * DH + i;
    float x1 = g_q[base], x2 = g_q[base + 32];
    g_q[base] = x1 * c - x2 * s;
    g_q[base + 32] = x2 * c + x1 * s;
}
__global__ void __launch_bounds__(128) k_rope_k() {
    int t = blockIdx.x;
    int h = threadIdx.x >> 5, i = threadIdx.x & 31;
    int pos = t & (SS - 1);
    float ang = (float)pos * g_invf[i];
    float s, c; sincosf(ang, &s, &c);
    size_t base = (size_t)t * KVD + h * DH + i;
    float x1 = g_k[base], x2 = g_k[base + 32];
    g_k[base] = x1 * c - x2 * s;
    g_k[base + 32] = x2 * c + x1 * s;
}

// ---------------------------------------------------------------------------
// Flash attention (fp32) -> g_ctx
// ---------------------------------------------------------------------------
__global__ void __launch_bounds__(128) k_attn() {
    int qt = blockIdx.x;
    int bh = blockIdx.y;
    int b = bh >> 4, h = bh & 15, hk = h >> 2;
    int tid = threadIdx.x;
    extern __shared__ float sm[];
    float* Ks = sm;
    float* Vs = sm + 4096;
    float* Sr = sm + 8192;

    int qi = qt * 128 + tid;
    int t  = b * SS + qi;
    float2 q2[32];
    {
        const float4* qp = (const float4*)(g_q + (size_t)t * DD + h * DH);
        #pragma unroll
        for (int u = 0; u < 16; u++) {
            float4 x = qp[u];
            q2[2 * u]     = make_float2(x.x * 0.125f, x.y * 0.125f);
            q2[2 * u + 1] = make_float2(x.z * 0.125f, x.w * 0.125f);
        }
    }
    float2 a2[32];
    #pragma unroll
    for (int d = 0; d < 32; d++) a2[d] = make_float2(0.f, 0.f);
    float m = -3e38f, l = 0.f;

    int jmax = 2 * qt + 1;
    for (int jt = 0; jt <= jmax; jt++) {
        int kb = b * SS + jt * 64;
        #pragma unroll
        for (int u = 0; u < 8; u++) {
            int lin = u * 128 + tid;
            int rw = lin >> 4, c4 = lin & 15;
            *(float4*)(Ks + rw * 64 + c4 * 4) =
                *(const float4*)(g_k + (size_t)(kb + rw) * KVD + hk * DH + c4 * 4);
            *(float4*)(Vs + rw * 64 + c4 * 4) =
                *(const float4*)(g_v + (size_t)(kb + rw) * KVD + hk * DH + c4 * 4);
        }
        __syncthreads();
        int lim = qi - jt * 64;
        if (lim >= 0) {
            int cmax = lim < 63 ? lim : 63;
            float smax = -3e38f;
            for (int c = 0; c <= cmax; c++) {
                const float4* kr = (const float4*)(Ks + c * 64);
                ull s2 = 0ull;
                #pragma unroll
                for (int d4 = 0; d4 < 16; d4++) {
                    float4 kv = kr[d4];
                    fma2(s2, *(ull*)&q2[2 * d4],     *(ull*)&kv.x);
                    fma2(s2, *(ull*)&q2[2 * d4 + 1], *(ull*)&kv.z);
                }
                float2 sr = up2(s2);
                float s = sr.x + sr.y;
                Sr[tid * 65 + c] = s;
                smax = fmaxf(smax, s);
            }
            float mnew = fmaxf(m, smax);
            float corr = __expf(m - mnew);
            l *= corr;
            #pragma unroll
            for (int d = 0; d < 32; d++) { a2[d].x *= corr; a2[d].y *= corr; }
            for (int c = 0; c <= cmax; c++) {
                float p = __expf(Sr[tid * 65 + c] - mnew);
                l += p;
                ull pd = pk2(p, p);
                const float4* vr = (const float4*)(Vs + c * 64);
                #pragma unroll
                for (int d4 = 0; d4 < 16; d4++) {
                    float4 vv = vr[d4];
                    fma2(*(ull*)&a2[2 * d4],     *(ull*)&vv.x, pd);
                    fma2(*(ull*)&a2[2 * d4 + 1], *(ull*)&vv.z, pd);
                }
            }
            m = mnew;
        }
        __syncthreads();
    }
    float inv = 1.0f / l;
    float4* op = (float4*)(g_ctx + (size_t)t * DD + h * DH);
    #pragma unroll
    for (int u = 0; u < 16; u++)
        op[u] = make_float4(a2[2 * u].x * inv, a2[2 * u].y * inv,
                            a2[2 * u + 1].x * inv, a2[2 * u + 1].y * inv);
}

// ---------------------------------------------------------------------------
// residual add + clip + RMSNorm2 -> g_res2, g_flat + flat hi/lo
// ---------------------------------------------------------------------------
__global__ void __launch_bounds__(256) k_post(const float* __restrict__ hidden,
                                              const float* __restrict__ w2) {
    int t = blockIdx.x, i = threadIdx.x;
    float4 hv = ((const float4*)(hidden + (size_t)t * DD))[i];
    float4 av = ((const float4*)(g_attn + (size_t)t * DD))[i];
    float4 s;
    s.x = fminf(fmaxf(hv.x + av.x, -100.f), 100.f);
    s.y = fminf(fmaxf(hv.y + av.y, -100.f), 100.f);
    s.z = fminf(fmaxf(hv.z + av.z, -100.f), 100.f);
    s.w = fminf(fmaxf(hv.w + av.w, -100.f), 100.f);
    ((float4*)(g_res2 + (size_t)t * DD))[i] = s;
    float ss = s.x * s.x + s.y * s.y + s.z * s.z + s.w * s.w;
    __shared__ float red[8];
    int lane = i & 31, wp = i >> 5;
    #pragma unroll
    for (int o = 16; o; o >>= 1) ss += __shfl_xor_sync(0xffffffffu, ss, o);
    if (!lane) red[wp] = ss;
    __syncthreads();
    if (i == 0) { float z = 0.f; for (int j = 0; j < 8; j++) z += red[j]; red[0] = z; }
    __syncthreads();
    float rs = rsqrtf(red[0] * (1.0f / DD) + EPS_RMS);
    float4 wv = ((const float4*)w2)[i];
    float4 f = make_float4(s.x * rs * wv.x, s.y * rs * wv.y, s.z * rs * wv.z, s.w * rs * wv.w);
    ((float4*)(g_flat + (size_t)t * DD))[i] = f;
    bf16 h0, l0, h1, l1, h2, l2, h3, l3;
    split_bf(f.x, h0, l0); split_bf(f.y, h1, l1);
    split_bf(f.z, h2, l2); split_bf(f.w, h3, l3);
    ((ushort4*)(g_flat_hi + (size_t)t * DD))[i] = pack4(h0, h1, h2, h3);
    ((ushort4*)(g_flat_lo + (size_t)t * DD))[i] = pack4(l0, l1, l2, l3);
}

// ---------------------------------------------------------------------------
// Router
// ---------------------------------------------------------------------------
__global__ void __launch_bounds__(256) k_router(const float* __restrict__ Wr) {
    int t = blockIdx.x;
    int lane = threadIdx.x & 31, w = threadIdx.x >> 5;
    const float* fr = g_flat + (size_t)t * DD;
    float s = 0.f;
    for (int d = lane; d < DD; d += 32) s += fr[d] * Wr[d * NEXP + w];
    #pragma unroll
    for (int o = 16; o; o >>= 1) s += __shfl_xor_sync(0xffffffffu, s, o);
    __shared__ float lg[NEXP];
    if (!lane) lg[w] = s;
    __syncthreads();
    if (threadIdx.x == 0) {
        float l0 = -3e38f; int i0 = 0;
        #pragma unroll
        for (int e2 = 0; e2 < NEXP; e2++) if (lg[e2] > l0) { l0 = lg[e2]; i0 = e2; }
        float l1 = -3e38f; int i1 = 0;
        #pragma unroll
        for (int e2 = 0; e2 < NEXP; e2++)
            if (e2 != i0 && lg[e2] > l1) { l1 = lg[e2]; i1 = e2; }
        float p1 = __expf(l1 - l0);
        float w0 = 1.0f / (1.0f + p1), w1 = p1 / (1.0f + p1);
        int pos0 = atomicAdd(&g_cnt[i0], 1);
        g_list[i0 * NT + pos0] = t;
        g_tok_e[t * 2] = i0; g_tok_i[t * 2] = pos0; g_tok_w[t * 2] = w0;
        int pos1 = atomicAdd(&g_cnt[i1], 1);
        g_list[i1 * NT + pos1] = t;
        g_tok_e[t * 2 + 1] = i1; g_tok_i[t * 2 + 1] = pos1; g_tok_w[t * 2 + 1] = w1;
    }
}

// ---------------------------------------------------------------------------
// SiLU(g)*u -> act hi/lo bf16
// ---------------------------------------------------------------------------
__global__ void __launch_bounds__(256) k_act() {
    int e = blockIdx.y, r = blockIdx.x;
    if (r >= g_cnt[e]) return;
    size_t base = ((size_t)e * NT + r) * FF;
    const float4* G4 = (const float4*)(g_G + base);
    const float4* U4 = (const float4*)(g_U + base);
    ushort4* AH = (ushort4*)(g_act_hi + base);
    ushort4* AL = (ushort4*)(g_act_lo + base);
    for (int f = threadIdx.x; f < FF / 4; f += 256) {
        float4 g = G4[f], u = U4[f];
        float a0 = g.x / (1.f + __expf(-g.x)) * u.x;
        float a1 = g.y / (1.f + __expf(-g.y)) * u.y;
        float a2 = g.z / (1.f + __expf(-g.z)) * u.z;
        float a3 = g.w / (1.f + __expf(-g.w)) * u.w;
        bf16 h0, l0, h1, l1, h2, l2, h3, l3;
        split_bf(a0, h0, l0); split_bf(a1, h1, l1);
        split_bf(a2, h2, l2); split_bf(a3, h3, l3);
        AH[f] = pack4(h0, h1, h2, h3);
        AL[f] = pack4(l0, l1, l2, l3);
    }
}

// ---------------------------------------------------------------------------
// Final combine
// ---------------------------------------------------------------------------
__global__ void __launch_bounds__(256) k_combine(float* __restrict__ out) {
    int t = blockIdx.x, i = threadIdx.x;
    int e0 = g_tok_e[t * 2],     i0 = g_tok_i[t * 2];     float w0 = g_tok_w[t * 2];
    int e1 = g_tok_e[t * 2 + 1], i1 = g_tok_i[t * 2 + 1]; float w1 = g_tok_w[t * 2 + 1];
    const float4* o0 = (const float4*)(g_O + ((size_t)e0 * NT + i0) * DD);
    const float4* o1 = (const float4*)(g_O + ((size_t)e1 * NT + i1) * DD);
    const float4* rr = (const float4*)(g_res2 + (size_t)t * DD);
    float4 a = rr[i], x = o0[i], y = o1[i], o;
    o.x = fminf(fmaxf(a.x + w0 * x.x + w1 * y.x, -100.f), 100.f);
    o.y = fminf(fmaxf(a.y + w0 * x.y + w1 * y.y, -100.f), 100.f);
    o.z = fminf(fmaxf(a.z + w0 * x.z + w1 * y.z, -100.f), 100.f);
    o.w = fminf(fmaxf(a.w + w0 * x.w + w1 * y.w, -100.f), 100.f);
    ((float4*)(out + (size_t)t * DD))[i] = o;
}

// ---------------------------------------------------------------------------
// Host launcher
// ---------------------------------------------------------------------------
extern "C" void kernel_launch(void* const* d_in, const int* in_sizes, int n_in,
                              void* d_out, int out_size) {
    const float* hidden = (const float*)d_in[0];
    const float* ln1    = (const float*)d_in[1];
    const float* ln2    = (const float*)d_in[2];
    const float* Wq     = (const float*)d_in[3];
    const float* Wk     = (const float*)d_in[4];
    const float* Wv     = (const float*)d_in[5];
    const float* Wo     = (const float*)d_in[6];
    const float* Wr     = (const float*)d_in[7];
    const float* Wg     = (const float*)d_in[8];
    const float* Wu     = (const float*)d_in[9];
    const float* Wd     = (const float*)d_in[10];
    float* out = (float*)d_out;
    (void)in_sizes; (void)n_in; (void)out_size;

    float *p_h1, *p_ctx, *p_attn, *p_G, *p_U, *p_O;
    int *p_lst, *p_cnt;
    bf16 *p_fh, *p_fl, *p_ah, *p_al;
    bf16 *p_wgh, *p_wgl, *p_wuh, *p_wul, *p_wdh, *p_wdl;
    cudaGetSymbolAddress((void**)&p_h1,  g_h1);
    cudaGetSymbolAddress((void**)&p_ctx, g_ctx);
    cudaGetSymbolAddress((void**)&p_attn,g_attn);
    cudaGetSymbolAddress((void**)&p_G,   g_G);
    cudaGetSymbolAddress((void**)&p_U,   g_U);
    cudaGetSymbolAddress((void**)&p_O,   g_O);
    cudaGetSymbolAddress((void**)&p_lst, g_list);
    cudaGetSymbolAddress((void**)&p_cnt, g_cnt);
    cudaGetSymbolAddress((void**)&p_fh,  g_flat_hi);
    cudaGetSymbolAddress((void**)&p_fl,  g_flat_lo);
    cudaGetSymbolAddress((void**)&p_ah,  g_act_hi);
    cudaGetSymbolAddress((void**)&p_al,  g_act_lo);
    cudaGetSymbolAddress((void**)&p_wgh, g_wgT_hi);
    cudaGetSymbolAddress((void**)&p_wgl, g_wgT_lo);
    cudaGetSymbolAddress((void**)&p_wuh, g_wuT_hi);
    cudaGetSymbolAddress((void**)&p_wul, g_wuT_lo);
    cudaGetSymbolAddress((void**)&p_wdh, g_wdT_hi);
    cudaGetSymbolAddress((void**)&p_wdl, g_wdT_lo);

    const int ATTN_SMEM = (4096 + 4096 + 128 * 65) * 4;   // 66048 B
    static int s_attr_done = 0;
    if (!s_attr_done) {
        cudaFuncSetAttribute(k_attn, cudaFuncAttributeMaxDynamicSharedMemorySize, ATTN_SMEM);
        cudaFuncSetAttribute(k_sgemm, cudaFuncAttributeMaxDynamicSharedMemorySize, SGEMM_SMEM);
        cudaFuncSetAttribute(k_sgemm_qkv, cudaFuncAttributeMaxDynamicSharedMemorySize, SGEMM_SMEM);
        s_attr_done = 1;
    }

    k_zero_init<<<1, 32>>>();

    // Weight transpose + bf16 split for MoE
    k_wt<<<dim3(FF / 32, DD / 32, NEXP), 256>>>(Wg, p_wgh, p_wgl, DD, FF,
                                                (size_t)DD * FF, (size_t)FF * DD);
    k_wt<<<dim3(FF / 32, DD / 32, NEXP), 256>>>(Wu, p_wuh, p_wul, DD, FF,
                                                (size_t)DD * FF, (size_t)FF * DD);
    k_wt<<<dim3(DD / 32, FF / 32, NEXP), 256>>>(Wd, p_wdh, p_wdl, FF, DD,
                                                (size_t)FF * DD, (size_t)DD * FF);

    k_rms1<<<NT, 256>>>(hidden, ln1);
    k_sgemm_qkv<<<dim3(12, NT / BM), 256, SGEMM_SMEM>>>(p_h1, Wq, Wk, Wv);
    k_rope_q<<<NT, 512>>>();
    k_rope_k<<<NT, 128>>>();
    k_attn<<<dim3(16, 32), 128, ATTN_SMEM>>>();
    k_sgemm<<<dim3(8, NT / BM), 256, SGEMM_SMEM>>>((const float*)p_ctx, Wo, p_attn,
                                                   NT, 1024, 1024);
    k_post<<<NT, 256>>>(hidden, ln2);
    k_router<<<NT, 256>>>(Wr);

    // MoE on warp-level tensor cores: G, U, then down-proj
    k_mma_gemm<<<dim3(FF / 128, NT / 128, NEXP), 256>>>(
        p_fh, p_fl, DD, (size_t)0,
        p_wgh, p_wgl, (size_t)FF * DD,
        p_G, FF, (size_t)NT * FF,
        0, DD, p_lst, p_cnt);
    k_mma_gemm<<<dim3(FF / 128, NT / 128, NEXP), 256>>>(
        p_fh, p_fl, DD, (size_t)0,
        p_wuh, p_wul, (size_t)FF * DD,
        p_U, FF, (size_t)NT * FF,
        0, DD, p_lst, p_cnt);
    k_act<<<dim3(NT, NEXP), 256>>>();
    k_mma_gemm<<<dim3(DD / 128, NT / 128, NEXP), 256>>>(
        p_ah, p_al, FF, (size_t)NT * FF,
        p_wdh, p_wdl, (size_t)DD * FF,
        p_O, DD, (size_t)NT * DD,
        0, FF, (const int*)0, p_cnt);

    k_combine<<<NT, 256>>>(out);
}

// round 13
// speedup vs baseline: 2.6626x; 1.2867x over previous
#include <cuda_runtime.h>
#include <cuda_bf16.h>
#include <math.h>
#include <stdint.h>

// Problem constants
#define NT   4096
#define DD   1024
#define SS   2048
#define NHQ  16
#define NHKV 4
#define DH   64
#define KVD  (NHKV * DH)   // 256
#define FF   2048
#define NEXP 8
#define EPS_RMS 1e-5f

typedef unsigned long long ull;
typedef __nv_bfloat16 bf16;

__device__ __forceinline__ ull pk2(float x, float y) {
    ull r; asm("mov.b64 %0, {%1, %2};" : "=l"(r) : "f"(x), "f"(y)); return r;
}
__device__ __forceinline__ void fma2(ull& c, ull a, ull b) {
    asm("fma.rn.f32x2 %0, %1, %2, %0;" : "+l"(c) : "l"(a), "l"(b));
}
__device__ __forceinline__ float2 up2(ull v) {
    float2 r; asm("mov.b64 {%0, %1}, %2;" : "=f"(r.x), "=f"(r.y) : "l"(v)); return r;
}
__device__ __forceinline__ uint32_t smem_u32(const void* p) {
    uint32_t a;
    asm("{ .reg .u64 t; cvta.to.shared.u64 t, %1; cvt.u32.u64 %0, t; }" : "=r"(a) : "l"(p));
    return a;
}
// warp-level tensor core primitives (sm_80+, valid on base sm_100)
__device__ __forceinline__ void ldm_x4(uint32_t r[4], uint32_t addr) {
    asm volatile("ldmatrix.sync.aligned.m8n8.x4.shared.b16 {%0,%1,%2,%3}, [%4];"
        : "=r"(r[0]), "=r"(r[1]), "=r"(r[2]), "=r"(r[3]) : "r"(addr));
}
__device__ __forceinline__ void mma16816(float c[4], const uint32_t a[4],
                                         uint32_t b0, uint32_t b1) {
    asm volatile("mma.sync.aligned.m16n8k16.row.col.f32.bf16.bf16.f32 "
        "{%0,%1,%2,%3}, {%4,%5,%6,%7}, {%8,%9}, {%0,%1,%2,%3};"
        : "+f"(c[0]), "+f"(c[1]), "+f"(c[2]), "+f"(c[3])
        : "r"(a[0]), "r"(a[1]), "r"(a[2]), "r"(a[3]), "r"(b0), "r"(b1));
}
__device__ __forceinline__ void split_bf(float x, bf16& h, bf16& l) {
    h = __float2bfloat16(x);
    l = __float2bfloat16(x - __bfloat162float(h));
}
__device__ __forceinline__ ushort4 pack4(bf16 a, bf16 b, bf16 c, bf16 d) {
    ushort4 s;
    s.x = __bfloat16_as_ushort(a); s.y = __bfloat16_as_ushort(b);
    s.z = __bfloat16_as_ushort(c); s.w = __bfloat16_as_ushort(d);
    return s;
}

// ---------------------------------------------------------------------------
// Scratch
// ---------------------------------------------------------------------------
__device__ __align__(16) float g_q   [(size_t)NT * DD];
__device__ __align__(16) float g_k   [(size_t)NT * KVD];
__device__ __align__(16) float g_v   [(size_t)NT * KVD];
__device__ __align__(16) float g_attn[(size_t)NT * DD];
__device__ __align__(16) float g_res2[(size_t)NT * DD];
__device__ __align__(16) float g_flat[(size_t)NT * DD];
__device__ __align__(16) float g_G   [(size_t)NEXP * NT * FF];
__device__ __align__(16) float g_U   [(size_t)NEXP * NT * FF];
__device__ __align__(16) float g_O   [(size_t)NEXP * NT * DD];
__device__ int   g_cnt [NEXP];
__device__ int   g_list[NEXP * NT];
__device__ int   g_tok_e[NT * 2];
__device__ int   g_tok_i[NT * 2];
__device__ float g_tok_w[NT * 2];
__device__ float g_invf[32];

// bf16 split buffers (activations)
__device__ __align__(16) bf16 g_h1_hi [(size_t)NT * DD];
__device__ __align__(16) bf16 g_h1_lo [(size_t)NT * DD];
__device__ __align__(16) bf16 g_ctx_hi[(size_t)NT * DD];
__device__ __align__(16) bf16 g_ctx_lo[(size_t)NT * DD];
__device__ __align__(16) bf16 g_flat_hi[(size_t)NT * DD];
__device__ __align__(16) bf16 g_flat_lo[(size_t)NT * DD];
__device__ __align__(16) bf16 g_act_hi[(size_t)NEXP * NT * FF];
__device__ __align__(16) bf16 g_act_lo[(size_t)NEXP * NT * FF];
// bf16 split transposed weights
__device__ __align__(16) bf16 g_wqT_hi[(size_t)DD * DD];
__device__ __align__(16) bf16 g_wqT_lo[(size_t)DD * DD];
__device__ __align__(16) bf16 g_wkT_hi[(size_t)KVD * DD];
__device__ __align__(16) bf16 g_wkT_lo[(size_t)KVD * DD];
__device__ __align__(16) bf16 g_wvT_hi[(size_t)KVD * DD];
__device__ __align__(16) bf16 g_wvT_lo[(size_t)KVD * DD];
__device__ __align__(16) bf16 g_woT_hi[(size_t)DD * DD];
__device__ __align__(16) bf16 g_woT_lo[(size_t)DD * DD];
__device__ __align__(16) bf16 g_wgT_hi[(size_t)NEXP * FF * DD];
__device__ __align__(16) bf16 g_wgT_lo[(size_t)NEXP * FF * DD];
__device__ __align__(16) bf16 g_wuT_hi[(size_t)NEXP * FF * DD];
__device__ __align__(16) bf16 g_wuT_lo[(size_t)NEXP * FF * DD];
__device__ __align__(16) bf16 g_wdT_hi[(size_t)NEXP * DD * FF];
__device__ __align__(16) bf16 g_wdT_lo[(size_t)NEXP * DD * FF];

// ---------------------------------------------------------------------------
__global__ void k_zero_init() {
    int i = threadIdx.x;
    if (i < NEXP) g_cnt[i] = 0;
    if (i < 32) {
        double ex = -((double)(2 * i) / 64.0) * 13.28771237954944939;
        g_invf[i] = (float)exp2(ex);
    }
}

// ---------------------------------------------------------------------------
// Weight transpose + bf16 hi/lo split: W[K][N] -> T[N][K]
// ---------------------------------------------------------------------------
__global__ void __launch_bounds__(256) k_wt(const float* __restrict__ W,
                                            bf16* __restrict__ Thi, bf16* __restrict__ Tlo,
                                            int Kd, int N, size_t wstride, size_t tstride) {
    int e = blockIdx.z;
    const float* Wb = W + (size_t)e * wstride;
    bf16* th = Thi + (size_t)e * tstride;
    bf16* tl = Tlo + (size_t)e * tstride;
    __shared__ float t[32][33];
    int kb = blockIdx.y * 32, nb = blockIdx.x * 32;
    int tx = threadIdx.x & 31, ty = threadIdx.x >> 5;
    #pragma unroll
    for (int j = 0; j < 4; j++)
        t[ty + j * 8][tx] = Wb[(size_t)(kb + ty + j * 8) * N + nb + tx];
    __syncthreads();
    #pragma unroll
    for (int j = 0; j < 4; j++) {
        int n = ty + j * 8;
        float x = t[tx][n];
        bf16 h, l; split_bf(x, h, l);
        th[(size_t)(nb + n) * Kd + kb + tx] = h;
        tl[(size_t)(nb + n) * Kd + kb + tx] = l;
    }
}

// ---------------------------------------------------------------------------
// RMSNorm 1 -> h1 hi/lo bf16
// ---------------------------------------------------------------------------
__global__ void __launch_bounds__(256) k_rms1(const float* __restrict__ x,
                                              const float* __restrict__ w) {
    int t = blockIdx.x, i = threadIdx.x;
    float4 v = ((const float4*)(x + (size_t)t * DD))[i];
    float ss = v.x * v.x + v.y * v.y + v.z * v.z + v.w * v.w;
    __shared__ float red[8];
    int lane = i & 31, wp = i >> 5;
    #pragma unroll
    for (int o = 16; o; o >>= 1) ss += __shfl_xor_sync(0xffffffffu, ss, o);
    if (!lane) red[wp] = ss;
    __syncthreads();
    if (i == 0) { float s = 0.f; for (int j = 0; j < 8; j++) s += red[j]; red[0] = s; }
    __syncthreads();
    float rs = rsqrtf(red[0] * (1.0f / DD) + EPS_RMS);
    float4 wv = ((const float4*)w)[i];
    float4 f = make_float4(v.x * rs * wv.x, v.y * rs * wv.y, v.z * rs * wv.z, v.w * rs * wv.w);
    bf16 h0, l0, h1, l1, h2, l2, h3, l3;
    split_bf(f.x, h0, l0); split_bf(f.y, h1, l1);
    split_bf(f.z, h2, l2); split_bf(f.w, h3, l3);
    ((ushort4*)(g_h1_hi + (size_t)t * DD))[i] = pack4(h0, h1, h2, h3);
    ((ushort4*)(g_h1_lo + (size_t)t * DD))[i] = pack4(l0, l1, l2, l3);
}

// ---------------------------------------------------------------------------
// bf16-split GEMM on warp-level tensor cores (mma.sync m16n8k16).
// C[128x128]/CTA = (Ahi+Alo) @ (Bhi+Blo)^T via 3 products (hh, hl, lh).
// Register-prefetch pipelined global->smem. 8 warps 2x4, warp tile 64x32.
// ---------------------------------------------------------------------------
#define LDP 40   // padded row length; 80B stride -> conflict-free ldmatrix
__global__ void __launch_bounds__(256, 1) k_mma_gemm(
    const bf16* __restrict__ Ahi, const bf16* __restrict__ Alo, int lda, size_t sAe,
    const bf16* __restrict__ Bhi, const bf16* __restrict__ Blo, size_t sBe,
    float* __restrict__ C, int ldc, size_t sCe,
    int M, int Kd,
    const int* __restrict__ rowlist, const int* __restrict__ counts)
{
    int e = blockIdx.z;
    int Me = counts ? counts[e] : M;
    int m0 = blockIdx.y * 128;
    if (m0 >= Me) return;
    int n0 = blockIdx.x * 128;

    __shared__ bf16 sAh[128 * LDP], sAl[128 * LDP];
    __shared__ bf16 sBh[128 * LDP], sBl[128 * LDP];

    int tid = threadIdx.x;
    int lane = tid & 31, wid = tid >> 5;
    int warp_m = wid >> 2, warp_n = wid & 3;

    int lrow0 = tid >> 2, lrow1 = lrow0 + 64, lch = tid & 3;
    int ra0 = m0 + lrow0; if (ra0 > Me - 1) ra0 = Me - 1;
    int ra1 = m0 + lrow1; if (ra1 > Me - 1) ra1 = Me - 1;
    size_t ga0 = rowlist ? (size_t)rowlist[e * NT + ra0] : (size_t)ra0;
    size_t ga1 = rowlist ? (size_t)rowlist[e * NT + ra1] : (size_t)ra1;
    const bf16* pa0h = Ahi + (size_t)e * sAe + ga0 * (size_t)lda + lch * 8;
    const bf16* pa0l = Alo + (size_t)e * sAe + ga0 * (size_t)lda + lch * 8;
    const bf16* pa1h = Ahi + (size_t)e * sAe + ga1 * (size_t)lda + lch * 8;
    const bf16* pa1l = Alo + (size_t)e * sAe + ga1 * (size_t)lda + lch * 8;
    const bf16* pb0h = Bhi + (size_t)e * sBe + (size_t)(n0 + lrow0) * Kd + lch * 8;
    const bf16* pb0l = Blo + (size_t)e * sBe + (size_t)(n0 + lrow0) * Kd + lch * 8;
    const bf16* pb1h = Bhi + (size_t)e * sBe + (size_t)(n0 + lrow1) * Kd + lch * 8;
    const bf16* pb1l = Blo + (size_t)e * sBe + (size_t)(n0 + lrow1) * Kd + lch * 8;

    int a_row = lane & 15;
    int a_col = (lane >> 4) * 8;
    int b_row = ((lane >> 4) * 8) + (lane & 7);
    int b_col = ((lane >> 3) & 1) * 8;

    float acc[4][4][4];
    #pragma unroll
    for (int mi = 0; mi < 4; mi++)
        #pragma unroll
        for (int ni = 0; ni < 4; ni++)
            #pragma unroll
            for (int r = 0; r < 4; r++) acc[mi][ni][r] = 0.f;

    uint4 rg[8];
    #define LOADG(kc) do { \
        rg[0] = *(const uint4*)(pa0h + (kc)); rg[1] = *(const uint4*)(pa1h + (kc)); \
        rg[2] = *(const uint4*)(pa0l + (kc)); rg[3] = *(const uint4*)(pa1l + (kc)); \
        rg[4] = *(const uint4*)(pb0h + (kc)); rg[5] = *(const uint4*)(pb1h + (kc)); \
        rg[6] = *(const uint4*)(pb0l + (kc)); rg[7] = *(const uint4*)(pb1l + (kc)); \
    } while (0)
    #define STORES() do { \
        *(uint4*)&sAh[lrow0 * LDP + lch * 8] = rg[0]; \
        *(uint4*)&sAh[lrow1 * LDP + lch * 8] = rg[1]; \
        *(uint4*)&sAl[lrow0 * LDP + lch * 8] = rg[2]; \
        *(uint4*)&sAl[lrow1 * LDP + lch * 8] = rg[3]; \
        *(uint4*)&sBh[lrow0 * LDP + lch * 8] = rg[4]; \
        *(uint4*)&sBh[lrow1 * LDP + lch * 8] = rg[5]; \
        *(uint4*)&sBl[lrow0 * LDP + lch * 8] = rg[6]; \
        *(uint4*)&sBl[lrow1 * LDP + lch * 8] = rg[7]; \
    } while (0)

    LOADG(0); STORES(); __syncthreads();

    for (int kc = 0; kc < Kd; kc += 32) {
        bool more = (kc + 32) < Kd;
        if (more) LOADG(kc + 32);

        #pragma unroll
        for (int ks = 0; ks < 2; ks++) {
            int kof = ks * 16;
            uint32_t ah[4][4], al[4][4];
            #pragma unroll
            for (int mi = 0; mi < 4; mi++) {
                int r = warp_m * 64 + mi * 16 + a_row;
                ldm_x4(ah[mi], smem_u32(&sAh[r * LDP + kof + a_col]));
                ldm_x4(al[mi], smem_u32(&sAl[r * LDP + kof + a_col]));
            }
            uint32_t bh[2][4], bl[2][4];
            #pragma unroll
            for (int p = 0; p < 2; p++) {
                int r = warp_n * 32 + p * 16 + b_row;
                ldm_x4(bh[p], smem_u32(&sBh[r * LDP + kof + b_col]));
                ldm_x4(bl[p], smem_u32(&sBl[r * LDP + kof + b_col]));
            }
            #pragma unroll
            for (int mi = 0; mi < 4; mi++)
                #pragma unroll
                for (int ni = 0; ni < 4; ni++) {
                    int p = ni >> 1, o = (ni & 1) * 2;
                    mma16816(acc[mi][ni], ah[mi], bh[p][o], bh[p][o + 1]);
                    mma16816(acc[mi][ni], ah[mi], bl[p][o], bl[p][o + 1]);
                    mma16816(acc[mi][ni], al[mi], bh[p][o], bh[p][o + 1]);
                }
        }
        if (more) {
            __syncthreads();
            STORES();
        }
        __syncthreads();
    }

    float* Cb = C + (size_t)e * sCe;
    #pragma unroll
    for (int mi = 0; mi < 4; mi++) {
        int r0 = m0 + warp_m * 64 + mi * 16 + (lane >> 2);
        #pragma unroll
        for (int ni = 0; ni < 4; ni++) {
            int cc = n0 + warp_n * 32 + ni * 8 + (lane & 3) * 2;
            if (r0 < Me)
                *(float2*)&Cb[(size_t)r0 * ldc + cc] = make_float2(acc[mi][ni][0], acc[mi][ni][1]);
            if (r0 + 8 < Me)
                *(float2*)&Cb[(size_t)(r0 + 8) * ldc + cc] = make_float2(acc[mi][ni][2], acc[mi][ni][3]);
        }
    }
}

// ---------------------------------------------------------------------------
// RoPE
// ---------------------------------------------------------------------------
__global__ void __launch_bounds__(512) k_rope_q() {
    int t = blockIdx.x;
    int h = threadIdx.x >> 5, i = threadIdx.x & 31;
    int pos = t & (SS - 1);
    float ang = (float)pos * g_invf[i];
    float s, c; sincosf(ang, &s, &c);
    size_t base = (size_t)t * DD + h * DH + i;
    float x1 = g_q[base], x2 = g_q[base + 32];
    g_q[base] = x1 * c - x2 * s;
    g_q[base + 32] = x2 * c + x1 * s;
}
__global__ void __launch_bounds__(128) k_rope_k() {
    int t = blockIdx.x;
    int h = threadIdx.x >> 5, i = threadIdx.x & 31;
    int pos = t & (SS - 1);
    float ang = (float)pos * g_invf[i];
    float s, c; sincosf(ang, &s, &c);
    size_t base = (size_t)t * KVD + h * DH + i;
    float x1 = g_k[base], x2 = g_k[base + 32];
    g_k[base] = x1 * c - x2 * s;
    g_k[base + 32] = x2 * c + x1 * s;
}

// ---------------------------------------------------------------------------
// Flash attention (fp32) -> ctx hi/lo bf16
// ---------------------------------------------------------------------------
__global__ void __launch_bounds__(128) k_attn() {
    int qt = blockIdx.x;
    int bh = blockIdx.y;
    int b = bh >> 4, h = bh & 15, hk = h >> 2;
    int tid = threadIdx.x;
    extern __shared__ float sm[];
    float* Ks = sm;
    float* Vs = sm + 4096;
    float* Sr = sm + 8192;

    int qi = qt * 128 + tid;
    int t  = b * SS + qi;
    float2 q2[32];
    {
        const float4* qp = (const float4*)(g_q + (size_t)t * DD + h * DH);
        #pragma unroll
        for (int u = 0; u < 16; u++) {
            float4 x = qp[u];
            q2[2 * u]     = make_float2(x.x * 0.125f, x.y * 0.125f);
            q2[2 * u + 1] = make_float2(x.z * 0.125f, x.w * 0.125f);
        }
    }
    float2 a2[32];
    #pragma unroll
    for (int d = 0; d < 32; d++) a2[d] = make_float2(0.f, 0.f);
    float m = -3e38f, l = 0.f;

    int jmax = 2 * qt + 1;
    for (int jt = 0; jt <= jmax; jt++) {
        int kb = b * SS + jt * 64;
        #pragma unroll
        for (int u = 0; u < 8; u++) {
            int lin = u * 128 + tid;
            int rw = lin >> 4, c4 = lin & 15;
            *(float4*)(Ks + rw * 64 + c4 * 4) =
                *(const float4*)(g_k + (size_t)(kb + rw) * KVD + hk * DH + c4 * 4);
            *(float4*)(Vs + rw * 64 + c4 * 4) =
                *(const float4*)(g_v + (size_t)(kb + rw) * KVD + hk * DH + c4 * 4);
        }
        __syncthreads();
        int lim = qi - jt * 64;
        if (lim >= 0) {
            int cmax = lim < 63 ? lim : 63;
            float smax = -3e38f;
            for (int c = 0; c <= cmax; c++) {
                const float4* kr = (const float4*)(Ks + c * 64);
                ull s2 = 0ull;
                #pragma unroll
                for (int d4 = 0; d4 < 16; d4++) {
                    float4 kv = kr[d4];
                    fma2(s2, *(ull*)&q2[2 * d4],     *(ull*)&kv.x);
                    fma2(s2, *(ull*)&q2[2 * d4 + 1], *(ull*)&kv.z);
                }
                float2 sr = up2(s2);
                float s = sr.x + sr.y;
                Sr[tid * 65 + c] = s;
                smax = fmaxf(smax, s);
            }
            float mnew = fmaxf(m, smax);
            float corr = __expf(m - mnew);
            l *= corr;
            #pragma unroll
            for (int d = 0; d < 32; d++) { a2[d].x *= corr; a2[d].y *= corr; }
            for (int c = 0; c <= cmax; c++) {
                float p = __expf(Sr[tid * 65 + c] - mnew);
                l += p;
                ull pd = pk2(p, p);
                const float4* vr = (const float4*)(Vs + c * 64);
                #pragma unroll
                for (int d4 = 0; d4 < 16; d4++) {
                    float4 vv = vr[d4];
                    fma2(*(ull*)&a2[2 * d4],     *(ull*)&vv.x, pd);
                    fma2(*(ull*)&a2[2 * d4 + 1], *(ull*)&vv.z, pd);
                }
            }
            m = mnew;
        }
        __syncthreads();
    }
    float inv = 1.0f / l;
    size_t ob = ((size_t)t * DD + h * DH) >> 2;
    #pragma unroll
    for (int u = 0; u < 16; u++) {
        float f0 = a2[2 * u].x * inv, f1 = a2[2 * u].y * inv;
        float f2 = a2[2 * u + 1].x * inv, f3 = a2[2 * u + 1].y * inv;
        bf16 h0, l0, h1, l1, h2, l2, h3, l3;
        split_bf(f0, h0, l0); split_bf(f1, h1, l1);
        split_bf(f2, h2, l2); split_bf(f3, h3, l3);
        ((ushort4*)g_ctx_hi)[ob + u] = pack4(h0, h1, h2, h3);
        ((ushort4*)g_ctx_lo)[ob + u] = pack4(l0, l1, l2, l3);
    }
}

// ---------------------------------------------------------------------------
// residual add + clip + RMSNorm2 -> g_res2, g_flat + flat hi/lo
// ---------------------------------------------------------------------------
__global__ void __launch_bounds__(256) k_post(const float* __restrict__ hidden,
                                              const float* __restrict__ w2) {
    int t = blockIdx.x, i = threadIdx.x;
    float4 hv = ((const float4*)(hidden + (size_t)t * DD))[i];
    float4 av = ((const float4*)(g_attn + (size_t)t * DD))[i];
    float4 s;
    s.x = fminf(fmaxf(hv.x + av.x, -100.f), 100.f);
    s.y = fminf(fmaxf(hv.y + av.y, -100.f), 100.f);
    s.z = fminf(fmaxf(hv.z + av.z, -100.f), 100.f);
    s.w = fminf(fmaxf(hv.w + av.w, -100.f), 100.f);
    ((float4*)(g_res2 + (size_t)t * DD))[i] = s;
    float ss = s.x * s.x + s.y * s.y + s.z * s.z + s.w * s.w;
    __shared__ float red[8];
    int lane = i & 31, wp = i >> 5;
    #pragma unroll
    for (int o = 16; o; o >>= 1) ss += __shfl_xor_sync(0xffffffffu, ss, o);
    if (!lane) red[wp] = ss;
    __syncthreads();
    if (i == 0) { float z = 0.f; for (int j = 0; j < 8; j++) z += red[j]; red[0] = z; }
    __syncthreads();
    float rs = rsqrtf(red[0] * (1.0f / DD) + EPS_RMS);
    float4 wv = ((const float4*)w2)[i];
    float4 f = make_float4(s.x * rs * wv.x, s.y * rs * wv.y, s.z * rs * wv.z, s.w * rs * wv.w);
    ((float4*)(g_flat + (size_t)t * DD))[i] = f;
    bf16 h0, l0, h1, l1, h2, l2, h3, l3;
    split_bf(f.x, h0, l0); split_bf(f.y, h1, l1);
    split_bf(f.z, h2, l2); split_bf(f.w, h3, l3);
    ((ushort4*)(g_flat_hi + (size_t)t * DD))[i] = pack4(h0, h1, h2, h3);
    ((ushort4*)(g_flat_lo + (size_t)t * DD))[i] = pack4(l0, l1, l2, l3);
}

// ---------------------------------------------------------------------------
// Router
// ---------------------------------------------------------------------------
__global__ void __launch_bounds__(256) k_router(const float* __restrict__ Wr) {
    int t = blockIdx.x;
    int lane = threadIdx.x & 31, w = threadIdx.x >> 5;
    const float* fr = g_flat + (size_t)t * DD;
    float s = 0.f;
    for (int d = lane; d < DD; d += 32) s += fr[d] * Wr[d * NEXP + w];
    #pragma unroll
    for (int o = 16; o; o >>= 1) s += __shfl_xor_sync(0xffffffffu, s, o);
    __shared__ float lg[NEXP];
    if (!lane) lg[w] = s;
    __syncthreads();
    if (threadIdx.x == 0) {
        float l0 = -3e38f; int i0 = 0;
        #pragma unroll
        for (int e2 = 0; e2 < NEXP; e2++) if (lg[e2] > l0) { l0 = lg[e2]; i0 = e2; }
        float l1 = -3e38f; int i1 = 0;
        #pragma unroll
        for (int e2 = 0; e2 < NEXP; e2++)
            if (e2 != i0 && lg[e2] > l1) { l1 = lg[e2]; i1 = e2; }
        float p1 = __expf(l1 - l0);
        float w0 = 1.0f / (1.0f + p1), w1 = p1 / (1.0f + p1);
        int pos0 = atomicAdd(&g_cnt[i0], 1);
        g_list[i0 * NT + pos0] = t;
        g_tok_e[t * 2] = i0; g_tok_i[t * 2] = pos0; g_tok_w[t * 2] = w0;
        int pos1 = atomicAdd(&g_cnt[i1], 1);
        g_list[i1 * NT + pos1] = t;
        g_tok_e[t * 2 + 1] = i1; g_tok_i[t * 2 + 1] = pos1; g_tok_w[t * 2 + 1] = w1;
    }
}

// ---------------------------------------------------------------------------
// SiLU(g)*u -> act hi/lo bf16
// ---------------------------------------------------------------------------
__global__ void __launch_bounds__(256) k_act() {
    int e = blockIdx.y, r = blockIdx.x;
    if (r >= g_cnt[e]) return;
    size_t base = ((size_t)e * NT + r) * FF;
    const float4* G4 = (const float4*)(g_G + base);
    const float4* U4 = (const float4*)(g_U + base);
    ushort4* AH = (ushort4*)(g_act_hi + base);
    ushort4* AL = (ushort4*)(g_act_lo + base);
    for (int f = threadIdx.x; f < FF / 4; f += 256) {
        float4 g = G4[f], u = U4[f];
        float a0 = g.x / (1.f + __expf(-g.x)) * u.x;
        float a1 = g.y / (1.f + __expf(-g.y)) * u.y;
        float a2 = g.z / (1.f + __expf(-g.z)) * u.z;
        float a3 = g.w / (1.f + __expf(-g.w)) * u.w;
        bf16 h0, l0, h1, l1, h2, l2, h3, l3;
        split_bf(a0, h0, l0); split_bf(a1, h1, l1);
        split_bf(a2, h2, l2); split_bf(a3, h3, l3);
        AH[f] = pack4(h0, h1, h2, h3);
        AL[f] = pack4(l0, l1, l2, l3);
    }
}

// ---------------------------------------------------------------------------
// Final combine
// ---------------------------------------------------------------------------
__global__ void __launch_bounds__(256) k_combine(float* __restrict__ out) {
    int t = blockIdx.x, i = threadIdx.x;
    int e0 = g_tok_e[t * 2],     i0 = g_tok_i[t * 2];     float w0 = g_tok_w[t * 2];
    int e1 = g_tok_e[t * 2 + 1], i1 = g_tok_i[t * 2 + 1]; float w1 = g_tok_w[t * 2 + 1];
    const float4* o0 = (const float4*)(g_O + ((size_t)e0 * NT + i0) * DD);
    const float4* o1 = (const float4*)(g_O + ((size_t)e1 * NT + i1) * DD);
    const float4* rr = (const float4*)(g_res2 + (size_t)t * DD);
    float4 a = rr[i], x = o0[i], y = o1[i], o;
    o.x = fminf(fmaxf(a.x + w0 * x.x + w1 * y.x, -100.f), 100.f);
    o.y = fminf(fmaxf(a.y + w0 * x.y + w1 * y.y, -100.f), 100.f);
    o.z = fminf(fmaxf(a.z + w0 * x.z + w1 * y.z, -100.f), 100.f);
    o.w = fminf(fmaxf(a.w + w0 * x.w + w1 * y.w, -100.f), 100.f);
    ((float4*)(out + (size_t)t * DD))[i] = o;
}

// ---------------------------------------------------------------------------
// Host launcher
// ---------------------------------------------------------------------------
extern "C" void kernel_launch(void* const* d_in, const int* in_sizes, int n_in,
                              void* d_out, int out_size) {
    const float* hidden = (const float*)d_in[0];
    const float* ln1    = (const float*)d_in[1];
    const float* ln2    = (const float*)d_in[2];
    const float* Wq     = (const float*)d_in[3];
    const float* Wk     = (const float*)d_in[4];
    const float* Wv     = (const float*)d_in[5];
    const float* Wo     = (const float*)d_in[6];
    const float* Wr     = (const float*)d_in[7];
    const float* Wg     = (const float*)d_in[8];
    const float* Wu     = (const float*)d_in[9];
    const float* Wd     = (const float*)d_in[10];
    float* out = (float*)d_out;
    (void)in_sizes; (void)n_in; (void)out_size;

    float *p_q, *p_k, *p_v, *p_attn, *p_G, *p_U, *p_O;
    int *p_lst, *p_cnt;
    bf16 *p_h1h, *p_h1l, *p_cth, *p_ctl, *p_fh, *p_fl, *p_ah, *p_al;
    bf16 *p_wqh, *p_wql, *p_wkh, *p_wkl, *p_wvh, *p_wvl, *p_woh, *p_wol;
    bf16 *p_wgh, *p_wgl, *p_wuh, *p_wul, *p_wdh, *p_wdl;
    cudaGetSymbolAddress((void**)&p_q,   g_q);
    cudaGetSymbolAddress((void**)&p_k,   g_k);
    cudaGetSymbolAddress((void**)&p_v,   g_v);
    cudaGetSymbolAddress((void**)&p_attn,g_attn);
    cudaGetSymbolAddress((void**)&p_G,   g_G);
    cudaGetSymbolAddress((void**)&p_U,   g_U);
    cudaGetSymbolAddress((void**)&p_O,   g_O);
    cudaGetSymbolAddress((void**)&p_lst, g_list);
    cudaGetSymbolAddress((void**)&p_cnt, g_cnt);
    cudaGetSymbolAddress((void**)&p_h1h, g_h1_hi);
    cudaGetSymbolAddress((void**)&p_h1l, g_h1_lo);
    cudaGetSymbolAddress((void**)&p_cth, g_ctx_hi);
    cudaGetSymbolAddress((void**)&p_ctl, g_ctx_lo);
    cudaGetSymbolAddress((void**)&p_fh,  g_flat_hi);
    cudaGetSymbolAddress((void**)&p_fl,  g_flat_lo);
    cudaGetSymbolAddress((void**)&p_ah,  g_act_hi);
    cudaGetSymbolAddress((void**)&p_al,  g_act_lo);
    cudaGetSymbolAddress((void**)&p_wqh, g_wqT_hi);
    cudaGetSymbolAddress((void**)&p_wql, g_wqT_lo);
    cudaGetSymbolAddress((void**)&p_wkh, g_wkT_hi);
    cudaGetSymbolAddress((void**)&p_wkl, g_wkT_lo);
    cudaGetSymbolAddress((void**)&p_wvh, g_wvT_hi);
    cudaGetSymbolAddress((void**)&p_wvl, g_wvT_lo);
    cudaGetSymbolAddress((void**)&p_woh, g_woT_hi);
    cudaGetSymbolAddress((void**)&p_wol, g_woT_lo);
    cudaGetSymbolAddress((void**)&p_wgh, g_wgT_hi);
    cudaGetSymbolAddress((void**)&p_wgl, g_wgT_lo);
    cudaGetSymbolAddress((void**)&p_wuh, g_wuT_hi);
    cudaGetSymbolAddress((void**)&p_wul, g_wuT_lo);
    cudaGetSymbolAddress((void**)&p_wdh, g_wdT_hi);
    cudaGetSymbolAddress((void**)&p_wdl, g_wdT_lo);

    const int ATTN_SMEM = (4096 + 4096 + 128 * 65) * 4;   // 66048 B
    static int s_attr_done = 0;
    if (!s_attr_done) {
        cudaFuncSetAttribute(k_attn, cudaFuncAttributeMaxDynamicSharedMemorySize, ATTN_SMEM);
        s_attr_done = 1;
    }

    k_zero_init<<<1, 32>>>();

    // Weight transpose + bf16 split (attention + MoE)
    k_wt<<<dim3(DD / 32, DD / 32, 1), 256>>>(Wq, p_wqh, p_wql, DD, DD, 0, 0);
    k_wt<<<dim3(KVD / 32, DD / 32, 1), 256>>>(Wk, p_wkh, p_wkl, DD, KVD, 0, 0);
    k_wt<<<dim3(KVD / 32, DD / 32, 1), 256>>>(Wv, p_wvh, p_wvl, DD, KVD, 0, 0);
    k_wt<<<dim3(DD / 32, DD / 32, 1), 256>>>(Wo, p_woh, p_wol, DD, DD, 0, 0);
    k_wt<<<dim3(FF / 32, DD / 32, NEXP), 256>>>(Wg, p_wgh, p_wgl, DD, FF,
                                                (size_t)DD * FF, (size_t)FF * DD);
    k_wt<<<dim3(FF / 32, DD / 32, NEXP), 256>>>(Wu, p_wuh, p_wul, DD, FF,
                                                (size_t)DD * FF, (size_t)FF * DD);
    k_wt<<<dim3(DD / 32, FF / 32, NEXP), 256>>>(Wd, p_wdh, p_wdl, FF, DD,
                                                (size_t)FF * DD, (size_t)DD * FF);

    k_rms1<<<NT, 256>>>(hidden, ln1);

    // QKV on tensor cores
    k_mma_gemm<<<dim3(DD / 128, NT / 128, 1), 256>>>(
        p_h1h, p_h1l, DD, 0, p_wqh, p_wql, 0, p_q, DD, 0, NT, DD, 0, 0);
    k_mma_gemm<<<dim3(KVD / 128, NT / 128, 1), 256>>>(
        p_h1h, p_h1l, DD, 0, p_wkh, p_wkl, 0, p_k, KVD, 0, NT, DD, 0, 0);
    k_mma_gemm<<<dim3(KVD / 128, NT / 128, 1), 256>>>(
        p_h1h, p_h1l, DD, 0, p_wvh, p_wvl, 0, p_v, KVD, 0, NT, DD, 0, 0);

    k_rope_q<<<NT, 512>>>();
    k_rope_k<<<NT, 128>>>();
    k_attn<<<dim3(16, 32), 128, ATTN_SMEM>>>();

    // Wo on tensor cores
    k_mma_gemm<<<dim3(DD / 128, NT / 128, 1), 256>>>(
        p_cth, p_ctl, DD, 0, p_woh, p_wol, 0, p_attn, DD, 0, NT, DD, 0, 0);

    k_post<<<NT, 256>>>(hidden, ln2);
    k_router<<<NT, 256>>>(Wr);

    // MoE on tensor cores
    k_mma_gemm<<<dim3(FF / 128, NT / 128, NEXP), 256>>>(
        p_fh, p_fl, DD, 0, p_wgh, p_wgl, (size_t)FF * DD,
        p_G, FF, (size_t)NT * FF, 0, DD, p_lst, p_cnt);
    k_mma_gemm<<<dim3(FF / 128, NT / 128, NEXP), 256>>>(
        p_fh, p_fl, DD, 0, p_wuh, p_wul, (size_t)FF * DD,
        p_U, FF, (size_t)NT * FF, 0, DD, p_lst, p_cnt);
    k_act<<<dim3(NT, NEXP), 256>>>();
    k_mma_gemm<<<dim3(DD / 128, NT / 128, NEXP), 256>>>(
        p_ah, p_al, FF, (size_t)NT * FF, p_wdh, p_wdl, (size_t)DD * FF,
        p_O, DD, (size_t)NT * DD, 0, FF, 0, p_cnt);

    k_combine<<<NT, 256>>>(out);
}

// round 14
// speedup vs baseline: 3.7130x; 1.3945x over previous
#include <cuda_runtime.h>
#include <cuda_bf16.h>
#include <math.h>
#include <stdint.h>

// Problem constants
#define NT   4096
#define DD   1024
#define SS   2048
#define NHQ  16
#define NHKV 4
#define DH   64
#define KVD  (NHKV * DH)   // 256
#define FF   2048
#define NEXP 8
#define EPS_RMS 1e-5f

typedef unsigned long long ull;
typedef __nv_bfloat16 bf16;

__device__ __forceinline__ uint32_t smem_u32(const void* p) {
    uint32_t a;
    asm("{ .reg .u64 t; cvta.to.shared.u64 t, %1; cvt.u32.u64 %0, t; }" : "=r"(a) : "l"(p));
    return a;
}
// warp-level tensor core primitives (sm_80+, valid on base sm_100)
__device__ __forceinline__ void ldm_x4(uint32_t r[4], uint32_t addr) {
    asm volatile("ldmatrix.sync.aligned.m8n8.x4.shared.b16 {%0,%1,%2,%3}, [%4];"
        : "=r"(r[0]), "=r"(r[1]), "=r"(r[2]), "=r"(r[3]) : "r"(addr));
}
__device__ __forceinline__ void ldm_x4_t(uint32_t r[4], uint32_t addr) {
    asm volatile("ldmatrix.sync.aligned.m8n8.x4.trans.shared.b16 {%0,%1,%2,%3}, [%4];"
        : "=r"(r[0]), "=r"(r[1]), "=r"(r[2]), "=r"(r[3]) : "r"(addr));
}
__device__ __forceinline__ void mma16816(float c[4], const uint32_t a[4],
                                         uint32_t b0, uint32_t b1) {
    asm volatile("mma.sync.aligned.m16n8k16.row.col.f32.bf16.bf16.f32 "
        "{%0,%1,%2,%3}, {%4,%5,%6,%7}, {%8,%9}, {%0,%1,%2,%3};"
        : "+f"(c[0]), "+f"(c[1]), "+f"(c[2]), "+f"(c[3])
        : "r"(a[0]), "r"(a[1]), "r"(a[2]), "r"(a[3]), "r"(b0), "r"(b1));
}
__device__ __forceinline__ void split_bf(float x, bf16& h, bf16& l) {
    h = __float2bfloat16(x);
    l = __float2bfloat16(x - __bfloat162float(h));
}
__device__ __forceinline__ ushort4 pack4(bf16 a, bf16 b, bf16 c, bf16 d) {
    ushort4 s;
    s.x = __bfloat16_as_ushort(a); s.y = __bfloat16_as_ushort(b);
    s.z = __bfloat16_as_ushort(c); s.w = __bfloat16_as_ushort(d);
    return s;
}
// pack two fp32 into bf16x2 register: low half = x, high half = y
__device__ __forceinline__ uint32_t pkbf2(float x, float y) {
    uint32_t r;
    asm("cvt.rn.bf16x2.f32 %0, %1, %2;" : "=r"(r) : "f"(y), "f"(x));
    return r;
}

// ---------------------------------------------------------------------------
// Scratch
// ---------------------------------------------------------------------------
__device__ __align__(16) float g_q   [(size_t)NT * DD];
__device__ __align__(16) float g_k   [(size_t)NT * KVD];
__device__ __align__(16) float g_v   [(size_t)NT * KVD];
__device__ __align__(16) float g_attn[(size_t)NT * DD];
__device__ __align__(16) float g_res2[(size_t)NT * DD];
__device__ __align__(16) float g_flat[(size_t)NT * DD];
__device__ __align__(16) float g_G   [(size_t)NEXP * NT * FF];
__device__ __align__(16) float g_U   [(size_t)NEXP * NT * FF];
__device__ __align__(16) float g_O   [(size_t)NEXP * NT * DD];
__device__ int   g_cnt [NEXP];
__device__ int   g_list[NEXP * NT];
__device__ int   g_tok_e[NT * 2];
__device__ int   g_tok_i[NT * 2];
__device__ float g_tok_w[NT * 2];
__device__ float g_invf[32];

// bf16 split buffers (activations)
__device__ __align__(16) bf16 g_h1_hi [(size_t)NT * DD];
__device__ __align__(16) bf16 g_h1_lo [(size_t)NT * DD];
__device__ __align__(16) bf16 g_qs_hi [(size_t)NT * DD];
__device__ __align__(16) bf16 g_qs_lo [(size_t)NT * DD];
__device__ __align__(16) bf16 g_ks_hi [(size_t)NT * KVD];
__device__ __align__(16) bf16 g_ks_lo [(size_t)NT * KVD];
__device__ __align__(16) bf16 g_vb    [(size_t)NT * KVD];
__device__ __align__(16) bf16 g_ctx_hi[(size_t)NT * DD];
__device__ __align__(16) bf16 g_ctx_lo[(size_t)NT * DD];
__device__ __align__(16) bf16 g_flat_hi[(size_t)NT * DD];
__device__ __align__(16) bf16 g_flat_lo[(size_t)NT * DD];
__device__ __align__(16) bf16 g_act_hi[(size_t)NEXP * NT * FF];
__device__ __align__(16) bf16 g_act_lo[(size_t)NEXP * NT * FF];
// bf16 split transposed weights
__device__ __align__(16) bf16 g_wqT_hi[(size_t)DD * DD];
__device__ __align__(16) bf16 g_wqT_lo[(size_t)DD * DD];
__device__ __align__(16) bf16 g_wkT_hi[(size_t)KVD * DD];
__device__ __align__(16) bf16 g_wkT_lo[(size_t)KVD * DD];
__device__ __align__(16) bf16 g_wvT_hi[(size_t)KVD * DD];
__device__ __align__(16) bf16 g_wvT_lo[(size_t)KVD * DD];
__device__ __align__(16) bf16 g_woT_hi[(size_t)DD * DD];
__device__ __align__(16) bf16 g_woT_lo[(size_t)DD * DD];
__device__ __align__(16) bf16 g_wgT_hi[(size_t)NEXP * FF * DD];
__device__ __align__(16) bf16 g_wgT_lo[(size_t)NEXP * FF * DD];
__device__ __align__(16) bf16 g_wuT_hi[(size_t)NEXP * FF * DD];
__device__ __align__(16) bf16 g_wuT_lo[(size_t)NEXP * FF * DD];
__device__ __align__(16) bf16 g_wdT_hi[(size_t)NEXP * DD * FF];
__device__ __align__(16) bf16 g_wdT_lo[(size_t)NEXP * DD * FF];

// ---------------------------------------------------------------------------
__global__ void k_zero_init() {
    int i = threadIdx.x;
    if (i < NEXP) g_cnt[i] = 0;
    if (i < 32) {
        double ex = -((double)(2 * i) / 64.0) * 13.28771237954944939;
        g_invf[i] = (float)exp2(ex);
    }
}

// ---------------------------------------------------------------------------
// Weight transpose + bf16 hi/lo split: W[K][N] -> T[N][K]
// ---------------------------------------------------------------------------
__global__ void __launch_bounds__(256) k_wt(const float* __restrict__ W,
                                            bf16* __restrict__ Thi, bf16* __restrict__ Tlo,
                                            int Kd, int N, size_t wstride, size_t tstride) {
    int e = blockIdx.z;
    const float* Wb = W + (size_t)e * wstride;
    bf16* th = Thi + (size_t)e * tstride;
    bf16* tl = Tlo + (size_t)e * tstride;
    __shared__ float t[32][33];
    int kb = blockIdx.y * 32, nb = blockIdx.x * 32;
    int tx = threadIdx.x & 31, ty = threadIdx.x >> 5;
    #pragma unroll
    for (int j = 0; j < 4; j++)
        t[ty + j * 8][tx] = Wb[(size_t)(kb + ty + j * 8) * N + nb + tx];
    __syncthreads();
    #pragma unroll
    for (int j = 0; j < 4; j++) {
        int n = ty + j * 8;
        float x = t[tx][n];
        bf16 h, l; split_bf(x, h, l);
        th[(size_t)(nb + n) * Kd + kb + tx] = h;
        tl[(size_t)(nb + n) * Kd + kb + tx] = l;
    }
}

// ---------------------------------------------------------------------------
// RMSNorm 1 -> h1 hi/lo bf16
// ---------------------------------------------------------------------------
__global__ void __launch_bounds__(256) k_rms1(const float* __restrict__ x,
                                              const float* __restrict__ w) {
    int t = blockIdx.x, i = threadIdx.x;
    float4 v = ((const float4*)(x + (size_t)t * DD))[i];
    float ss = v.x * v.x + v.y * v.y + v.z * v.z + v.w * v.w;
    __shared__ float red[8];
    int lane = i & 31, wp = i >> 5;
    #pragma unroll
    for (int o = 16; o; o >>= 1) ss += __shfl_xor_sync(0xffffffffu, ss, o);
    if (!lane) red[wp] = ss;
    __syncthreads();
    if (i == 0) { float s = 0.f; for (int j = 0; j < 8; j++) s += red[j]; red[0] = s; }
    __syncthreads();
    float rs = rsqrtf(red[0] * (1.0f / DD) + EPS_RMS);
    float4 wv = ((const float4*)w)[i];
    float4 f = make_float4(v.x * rs * wv.x, v.y * rs * wv.y, v.z * rs * wv.z, v.w * rs * wv.w);
    bf16 h0, l0, h1, l1, h2, l2, h3, l3;
    split_bf(f.x, h0, l0); split_bf(f.y, h1, l1);
    split_bf(f.z, h2, l2); split_bf(f.w, h3, l3);
    ((ushort4*)(g_h1_hi + (size_t)t * DD))[i] = pack4(h0, h1, h2, h3);
    ((ushort4*)(g_h1_lo + (size_t)t * DD))[i] = pack4(l0, l1, l2, l3);
}

// ---------------------------------------------------------------------------
// bf16-split GEMM on warp-level tensor cores (mma.sync m16n8k16).
// ---------------------------------------------------------------------------
#define LDP 40
__global__ void __launch_bounds__(256, 1) k_mma_gemm(
    const bf16* __restrict__ Ahi, const bf16* __restrict__ Alo, int lda, size_t sAe,
    const bf16* __restrict__ Bhi, const bf16* __restrict__ Blo, size_t sBe,
    float* __restrict__ C, int ldc, size_t sCe,
    int M, int Kd,
    const int* __restrict__ rowlist, const int* __restrict__ counts)
{
    int e = blockIdx.z;
    int Me = counts ? counts[e] : M;
    int m0 = blockIdx.y * 128;
    if (m0 >= Me) return;
    int n0 = blockIdx.x * 128;

    __shared__ bf16 sAh[128 * LDP], sAl[128 * LDP];
    __shared__ bf16 sBh[128 * LDP], sBl[128 * LDP];

    int tid = threadIdx.x;
    int lane = tid & 31, wid = tid >> 5;
    int warp_m = wid >> 2, warp_n = wid & 3;

    int lrow0 = tid >> 2, lrow1 = lrow0 + 64, lch = tid & 3;
    int ra0 = m0 + lrow0; if (ra0 > Me - 1) ra0 = Me - 1;
    int ra1 = m0 + lrow1; if (ra1 > Me - 1) ra1 = Me - 1;
    size_t ga0 = rowlist ? (size_t)rowlist[e * NT + ra0] : (size_t)ra0;
    size_t ga1 = rowlist ? (size_t)rowlist[e * NT + ra1] : (size_t)ra1;
    const bf16* pa0h = Ahi + (size_t)e * sAe + ga0 * (size_t)lda + lch * 8;
    const bf16* pa0l = Alo + (size_t)e * sAe + ga0 * (size_t)lda + lch * 8;
    const bf16* pa1h = Ahi + (size_t)e * sAe + ga1 * (size_t)lda + lch * 8;
    const bf16* pa1l = Alo + (size_t)e * sAe + ga1 * (size_t)lda + lch * 8;
    const bf16* pb0h = Bhi + (size_t)e * sBe + (size_t)(n0 + lrow0) * Kd + lch * 8;
    const bf16* pb0l = Blo + (size_t)e * sBe + (size_t)(n0 + lrow0) * Kd + lch * 8;
    const bf16* pb1h = Bhi + (size_t)e * sBe + (size_t)(n0 + lrow1) * Kd + lch * 8;
    const bf16* pb1l = Blo + (size_t)e * sBe + (size_t)(n0 + lrow1) * Kd + lch * 8;

    int a_row = lane & 15;
    int a_col = (lane >> 4) * 8;
    int b_row = ((lane >> 4) * 8) + (lane & 7);
    int b_col = ((lane >> 3) & 1) * 8;

    float acc[4][4][4];
    #pragma unroll
    for (int mi = 0; mi < 4; mi++)
        #pragma unroll
        for (int ni = 0; ni < 4; ni++)
            #pragma unroll
            for (int r = 0; r < 4; r++) acc[mi][ni][r] = 0.f;

    uint4 rg[8];
    #define LOADG(kc) do { \
        rg[0] = *(const uint4*)(pa0h + (kc)); rg[1] = *(const uint4*)(pa1h + (kc)); \
        rg[2] = *(const uint4*)(pa0l + (kc)); rg[3] = *(const uint4*)(pa1l + (kc)); \
        rg[4] = *(const uint4*)(pb0h + (kc)); rg[5] = *(const uint4*)(pb1h + (kc)); \
        rg[6] = *(const uint4*)(pb0l + (kc)); rg[7] = *(const uint4*)(pb1l + (kc)); \
    } while (0)
    #define STORES() do { \
        *(uint4*)&sAh[lrow0 * LDP + lch * 8] = rg[0]; \
        *(uint4*)&sAh[lrow1 * LDP + lch * 8] = rg[1]; \
        *(uint4*)&sAl[lrow0 * LDP + lch * 8] = rg[2]; \
        *(uint4*)&sAl[lrow1 * LDP + lch * 8] = rg[3]; \
        *(uint4*)&sBh[lrow0 * LDP + lch * 8] = rg[4]; \
        *(uint4*)&sBh[lrow1 * LDP + lch * 8] = rg[5]; \
        *(uint4*)&sBl[lrow0 * LDP + lch * 8] = rg[6]; \
        *(uint4*)&sBl[lrow1 * LDP + lch * 8] = rg[7]; \
    } while (0)

    LOADG(0); STORES(); __syncthreads();

    for (int kc = 0; kc < Kd; kc += 32) {
        bool more = (kc + 32) < Kd;
        if (more) LOADG(kc + 32);

        #pragma unroll
        for (int ks = 0; ks < 2; ks++) {
            int kof = ks * 16;
            uint32_t ah[4][4], al[4][4];
            #pragma unroll
            for (int mi = 0; mi < 4; mi++) {
                int r = warp_m * 64 + mi * 16 + a_row;
                ldm_x4(ah[mi], smem_u32(&sAh[r * LDP + kof + a_col]));
                ldm_x4(al[mi], smem_u32(&sAl[r * LDP + kof + a_col]));
            }
            uint32_t bh[2][4], bl[2][4];
            #pragma unroll
            for (int p = 0; p < 2; p++) {
                int r = warp_n * 32 + p * 16 + b_row;
                ldm_x4(bh[p], smem_u32(&sBh[r * LDP + kof + b_col]));
                ldm_x4(bl[p], smem_u32(&sBl[r * LDP + kof + b_col]));
            }
            #pragma unroll
            for (int mi = 0; mi < 4; mi++)
                #pragma unroll
                for (int ni = 0; ni < 4; ni++) {
                    int p = ni >> 1, o = (ni & 1) * 2;
                    mma16816(acc[mi][ni], ah[mi], bh[p][o], bh[p][o + 1]);
                    mma16816(acc[mi][ni], ah[mi], bl[p][o], bl[p][o + 1]);
                    mma16816(acc[mi][ni], al[mi], bh[p][o], bh[p][o + 1]);
                }
        }
        if (more) {
            __syncthreads();
            STORES();
        }
        __syncthreads();
    }

    float* Cb = C + (size_t)e * sCe;
    #pragma unroll
    for (int mi = 0; mi < 4; mi++) {
        int r0 = m0 + warp_m * 64 + mi * 16 + (lane >> 2);
        #pragma unroll
        for (int ni = 0; ni < 4; ni++) {
            int cc = n0 + warp_n * 32 + ni * 8 + (lane & 3) * 2;
            if (r0 < Me)
                *(float2*)&Cb[(size_t)r0 * ldc + cc] = make_float2(acc[mi][ni][0], acc[mi][ni][1]);
            if (r0 + 8 < Me)
                *(float2*)&Cb[(size_t)(r0 + 8) * ldc + cc] = make_float2(acc[mi][ni][2], acc[mi][ni][3]);
        }
    }
}

// ---------------------------------------------------------------------------
// RoPE -> bf16 split buffers (q scaled by 1/8)
// ---------------------------------------------------------------------------
__global__ void __launch_bounds__(512) k_rope_q() {
    int t = blockIdx.x;
    int h = threadIdx.x >> 5, i = threadIdx.x & 31;
    int pos = t & (SS - 1);
    float ang = (float)pos * g_invf[i];
    float s, c; sincosf(ang, &s, &c);
    size_t base = (size_t)t * DD + h * DH + i;
    float x1 = g_q[base], x2 = g_q[base + 32];
    float o1 = (x1 * c - x2 * s) * 0.125f;
    float o2 = (x2 * c + x1 * s) * 0.125f;
    bf16 h1, l1, h2, l2;
    split_bf(o1, h1, l1); split_bf(o2, h2, l2);
    g_qs_hi[base] = h1; g_qs_lo[base] = l1;
    g_qs_hi[base + 32] = h2; g_qs_lo[base + 32] = l2;
}
__global__ void __launch_bounds__(128) k_rope_k() {
    int t = blockIdx.x;
    int h = threadIdx.x >> 5, i = threadIdx.x & 31;
    int pos = t & (SS - 1);
    float ang = (float)pos * g_invf[i];
    float s, c; sincosf(ang, &s, &c);
    size_t base = (size_t)t * KVD + h * DH + i;
    float x1 = g_k[base], x2 = g_k[base + 32];
    float o1 = x1 * c - x2 * s;
    float o2 = x2 * c + x1 * s;
    bf16 h1, l1, h2, l2;
    split_bf(o1, h1, l1); split_bf(o2, h2, l2);
    g_ks_hi[base] = h1; g_ks_lo[base] = l1;
    g_ks_hi[base + 32] = h2; g_ks_lo[base + 32] = l2;
}
__global__ void __launch_bounds__(256) k_cvt_v() {
    size_t i = (size_t)blockIdx.x * 256 + threadIdx.x;   // of NT*KVD/4
    float4 v = ((const float4*)g_v)[i];
    ((ushort4*)g_vb)[i] = pack4(__float2bfloat16(v.x), __float2bfloat16(v.y),
                                __float2bfloat16(v.z), __float2bfloat16(v.w));
}

// ---------------------------------------------------------------------------
// Flash attention on mma.sync. CTA: 64 q-rows x one (b,h). 4 warps; warp w
// owns q rows [w*16, w*16+16) -> warp-local online softmax.
// S = Q@K^T bf16-split (3 mma); P, V plain bf16 (1 mma). -> ctx hi/lo bf16.
// ---------------------------------------------------------------------------
#define LDA 72   // padded row (elements): 144B stride, conflict-free ldmatrix
__global__ void __launch_bounds__(128) k_attn_mma() {
    int qt = blockIdx.x;                       // 0..31
    int bh = blockIdx.y;
    int b = bh >> 4, h = bh & 15, hk = h >> 2;
    int tid = threadIdx.x, lane = tid & 31, w = tid >> 5;

    __shared__ bf16 sQh[64 * LDA], sQl[64 * LDA];
    __shared__ bf16 sKh[64 * LDA], sKl[64 * LDA], sV[64 * LDA];

    // load Q tile (rows qt*64.., head cols)
    #pragma unroll
    for (int i = 0; i < 4; i++) {
        int idx = tid + i * 128;               // 0..511
        int r = idx >> 3, c8 = idx & 7;
        size_t g = (size_t)(b * SS + qt * 64 + r) * DD + h * DH + c8 * 8;
        *(uint4*)&sQh[r * LDA + c8 * 8] = *(const uint4*)(g_qs_hi + g);
        *(uint4*)&sQl[r * LDA + c8 * 8] = *(const uint4*)(g_qs_lo + g);
    }
    __syncthreads();

    int a_row = lane & 15, a_col = (lane >> 4) * 8;
    int b_row = ((lane >> 4) * 8) + (lane & 7), b_col = ((lane >> 3) & 1) * 8;

    uint32_t qh[4][4], ql[4][4];
    #pragma unroll
    for (int kc = 0; kc < 4; kc++) {
        ldm_x4(qh[kc], smem_u32(&sQh[(w * 16 + a_row) * LDA + kc * 16 + a_col]));
        ldm_x4(ql[kc], smem_u32(&sQl[(w * 16 + a_row) * LDA + kc * 16 + a_col]));
    }
    __syncthreads();   // Q smem no longer needed (frags in regs)

    float m0r = -1e30f, m1r = -1e30f, l0r = 0.f, l1r = 0.f;
    float acc[8][4];
    #pragma unroll
    for (int nt = 0; nt < 8; nt++)
        #pragma unroll
        for (int r = 0; r < 4; r++) acc[nt][r] = 0.f;

    int qrow0 = qt * 64 + w * 16 + (lane >> 2);

    for (int jt = 0; jt <= qt; jt++) {
        // load K hi/lo + V tile (64 keys x 64 d)
        #pragma unroll
        for (int i = 0; i < 4; i++) {
            int idx = tid + i * 128;
            int r = idx >> 3, c8 = idx & 7;
            size_t g = (size_t)(b * SS + jt * 64 + r) * KVD + hk * DH + c8 * 8;
            *(uint4*)&sKh[r * LDA + c8 * 8] = *(const uint4*)(g_ks_hi + g);
            *(uint4*)&sKl[r * LDA + c8 * 8] = *(const uint4*)(g_ks_lo + g);
            *(uint4*)&sV [r * LDA + c8 * 8] = *(const uint4*)(g_vb  + g);
        }
        __syncthreads();

        // S = Q @ K^T (bf16-split: hh + hl + lh)
        float s[8][4];
        #pragma unroll
        for (int nt = 0; nt < 8; nt++)
            #pragma unroll
            for (int r = 0; r < 4; r++) s[nt][r] = 0.f;
        #pragma unroll
        for (int kc = 0; kc < 4; kc++) {
            #pragma unroll
            for (int kg = 0; kg < 4; kg++) {
                uint32_t kbh[4], kbl[4];
                ldm_x4(kbh, smem_u32(&sKh[(kg * 16 + b_row) * LDA + kc * 16 + b_col]));
                ldm_x4(kbl, smem_u32(&sKl[(kg * 16 + b_row) * LDA + kc * 16 + b_col]));
                #pragma unroll
                for (int half = 0; half < 2; half++) {
                    int nt = kg * 2 + half, o = half * 2;
                    mma16816(s[nt], qh[kc], kbh[o], kbh[o + 1]);
                    mma16816(s[nt], qh[kc], kbl[o], kbl[o + 1]);
                    mma16816(s[nt], ql[kc], kbh[o], kbh[o + 1]);
                }
            }
        }

        // causal mask on diagonal tile
        if (jt == qt) {
            #pragma unroll
            for (int nt = 0; nt < 8; nt++) {
                int kcol = jt * 64 + nt * 8 + (lane & 3) * 2;
                if (kcol     > qrow0)     s[nt][0] = -1e30f;
                if (kcol + 1 > qrow0)     s[nt][1] = -1e30f;
                if (kcol     > qrow0 + 8) s[nt][2] = -1e30f;
                if (kcol + 1 > qrow0 + 8) s[nt][3] = -1e30f;
            }
        }

        // row max (quad reduce)
        float mx0 = -1e30f, mx1 = -1e30f;
        #pragma unroll
        for (int nt = 0; nt < 8; nt++) {
            mx0 = fmaxf(mx0, fmaxf(s[nt][0], s[nt][1]));
            mx1 = fmaxf(mx1, fmaxf(s[nt][2], s[nt][3]));
        }
        #pragma unroll
        for (int o = 1; o <= 2; o <<= 1) {
            mx0 = fmaxf(mx0, __shfl_xor_sync(0xffffffffu, mx0, o));
            mx1 = fmaxf(mx1, __shfl_xor_sync(0xffffffffu, mx1, o));
        }
        float mn0 = fmaxf(m0r, mx0), mn1 = fmaxf(m1r, mx1);
        float c0 = __expf(m0r - mn0), c1 = __expf(m1r - mn1);
        m0r = mn0; m1r = mn1;
        l0r *= c0; l1r *= c1;
        #pragma unroll
        for (int nt = 0; nt < 8; nt++) {
            acc[nt][0] *= c0; acc[nt][1] *= c0;
            acc[nt][2] *= c1; acc[nt][3] *= c1;
        }

        // P = exp(S - m), pack to A-frags; accumulate row sums
        uint32_t pa[4][4];
        float sum0 = 0.f, sum1 = 0.f;
        #pragma unroll
        for (int nt = 0; nt < 8; nt++) {
            float p0 = __expf(s[nt][0] - mn0), p1 = __expf(s[nt][1] - mn0);
            float p2 = __expf(s[nt][2] - mn1), p3 = __expf(s[nt][3] - mn1);
            sum0 += p0 + p1; sum1 += p2 + p3;
            pa[nt >> 1][(nt & 1) * 2 + 0] = pkbf2(p0, p1);
            pa[nt >> 1][(nt & 1) * 2 + 1] = pkbf2(p2, p3);
        }
        #pragma unroll
        for (int o = 1; o <= 2; o <<= 1) {
            sum0 += __shfl_xor_sync(0xffffffffu, sum0, o);
            sum1 += __shfl_xor_sync(0xffffffffu, sum1, o);
        }
        l0r += sum0; l1r += sum1;

        // O += P @ V  (V B-frags via ldmatrix.trans)
        #pragma unroll
        for (int kc = 0; kc < 4; kc++) {
            #pragma unroll
            for (int dp = 0; dp < 4; dp++) {
                uint32_t vb4[4];
                ldm_x4_t(vb4, smem_u32(&sV[(kc * 16 + (lane & 15)) * LDA + dp * 16 + (lane >> 4) * 8]));
                mma16816(acc[dp * 2],     pa[kc], vb4[0], vb4[1]);
                mma16816(acc[dp * 2 + 1], pa[kc], vb4[2], vb4[3]);
            }
        }
        __syncthreads();   // before next tile overwrites K/V
    }

    // epilogue: normalize, split, store ctx hi/lo
    float inv0 = 1.0f / l0r, inv1 = 1.0f / l1r;
    int t0 = b * SS + qrow0;
    #pragma unroll
    for (int nt = 0; nt < 8; nt++) {
        int d = h * DH + nt * 8 + (lane & 3) * 2;
        float f0 = acc[nt][0] * inv0, f1 = acc[nt][1] * inv0;
        float f2 = acc[nt][2] * inv1, f3 = acc[nt][3] * inv1;
        bf16 h0, l0, h1, l1, h2, l2, h3, l3;
        split_bf(f0, h0, l0); split_bf(f1, h1, l1);
        split_bf(f2, h2, l2); split_bf(f3, h3, l3);
        ushort2 u;
        u.x = __bfloat16_as_ushort(h0); u.y = __bfloat16_as_ushort(h1);
        *(ushort2*)&g_ctx_hi[(size_t)t0 * DD + d] = u;
        u.x = __bfloat16_as_ushort(l0); u.y = __bfloat16_as_ushort(l1);
        *(ushort2*)&g_ctx_lo[(size_t)t0 * DD + d] = u;
        u.x = __bfloat16_as_ushort(h2); u.y = __bfloat16_as_ushort(h3);
        *(ushort2*)&g_ctx_hi[(size_t)(t0 + 8) * DD + d] = u;
        u.x = __bfloat16_as_ushort(l2); u.y = __bfloat16_as_ushort(l3);
        *(ushort2*)&g_ctx_lo[(size_t)(t0 + 8) * DD + d] = u;
    }
}

// ---------------------------------------------------------------------------
// residual add + clip + RMSNorm2 -> g_res2, g_flat + flat hi/lo
// ---------------------------------------------------------------------------
__global__ void __launch_bounds__(256) k_post(const float* __restrict__ hidden,
                                              const float* __restrict__ w2) {
    int t = blockIdx.x, i = threadIdx.x;
    float4 hv = ((const float4*)(hidden + (size_t)t * DD))[i];
    float4 av = ((const float4*)(g_attn + (size_t)t * DD))[i];
    float4 s;
    s.x = fminf(fmaxf(hv.x + av.x, -100.f), 100.f);
    s.y = fminf(fmaxf(hv.y + av.y, -100.f), 100.f);
    s.z = fminf(fmaxf(hv.z + av.z, -100.f), 100.f);
    s.w = fminf(fmaxf(hv.w + av.w, -100.f), 100.f);
    ((float4*)(g_res2 + (size_t)t * DD))[i] = s;
    float ss = s.x * s.x + s.y * s.y + s.z * s.z + s.w * s.w;
    __shared__ float red[8];
    int lane = i & 31, wp = i >> 5;
    #pragma unroll
    for (int o = 16; o; o >>= 1) ss += __shfl_xor_sync(0xffffffffu, ss, o);
    if (!lane) red[wp] = ss;
    __syncthreads();
    if (i == 0) { float z = 0.f; for (int j = 0; j < 8; j++) z += red[j]; red[0] = z; }
    __syncthreads();
    float rs = rsqrtf(red[0] * (1.0f / DD) + EPS_RMS);
    float4 wv = ((const float4*)w2)[i];
    float4 f = make_float4(s.x * rs * wv.x, s.y * rs * wv.y, s.z * rs * wv.z, s.w * rs * wv.w);
    ((float4*)(g_flat + (size_t)t * DD))[i] = f;
    bf16 h0, l0, h1, l1, h2, l2, h3, l3;
    split_bf(f.x, h0, l0); split_bf(f.y, h1, l1);
    split_bf(f.z, h2, l2); split_bf(f.w, h3, l3);
    ((ushort4*)(g_flat_hi + (size_t)t * DD))[i] = pack4(h0, h1, h2, h3);
    ((ushort4*)(g_flat_lo + (size_t)t * DD))[i] = pack4(l0, l1, l2, l3);
}

// ---------------------------------------------------------------------------
// Router
// ---------------------------------------------------------------------------
__global__ void __launch_bounds__(256) k_router(const float* __restrict__ Wr) {
    int t = blockIdx.x;
    int lane = threadIdx.x & 31, w = threadIdx.x >> 5;
    const float* fr = g_flat + (size_t)t * DD;
    float s = 0.f;
    for (int d = lane; d < DD; d += 32) s += fr[d] * Wr[d * NEXP + w];
    #pragma unroll
    for (int o = 16; o; o >>= 1) s += __shfl_xor_sync(0xffffffffu, s, o);
    __shared__ float lg[NEXP];
    if (!lane) lg[w] = s;
    __syncthreads();
    if (threadIdx.x == 0) {
        float l0 = -3e38f; int i0 = 0;
        #pragma unroll
        for (int e2 = 0; e2 < NEXP; e2++) if (lg[e2] > l0) { l0 = lg[e2]; i0 = e2; }
        float l1 = -3e38f; int i1 = 0;
        #pragma unroll
        for (int e2 = 0; e2 < NEXP; e2++)
            if (e2 != i0 && lg[e2] > l1) { l1 = lg[e2]; i1 = e2; }
        float p1 = __expf(l1 - l0);
        float w0 = 1.0f / (1.0f + p1), w1 = p1 / (1.0f + p1);
        int pos0 = atomicAdd(&g_cnt[i0], 1);
        g_list[i0 * NT + pos0] = t;
        g_tok_e[t * 2] = i0; g_tok_i[t * 2] = pos0; g_tok_w[t * 2] = w0;
        int pos1 = atomicAdd(&g_cnt[i1], 1);
        g_list[i1 * NT + pos1] = t;
        g_tok_e[t * 2 + 1] = i1; g_tok_i[t * 2 + 1] = pos1; g_tok_w[t * 2 + 1] = w1;
    }
}

// ---------------------------------------------------------------------------
// SiLU(g)*u -> act hi/lo bf16
// ---------------------------------------------------------------------------
__global__ void __launch_bounds__(256) k_act() {
    int e = blockIdx.y, r = blockIdx.x;
    if (r >= g_cnt[e]) return;
    size_t base = ((size_t)e * NT + r) * FF;
    const float4* G4 = (const float4*)(g_G + base);
    const float4* U4 = (const float4*)(g_U + base);
    ushort4* AH = (ushort4*)(g_act_hi + base);
    ushort4* AL = (ushort4*)(g_act_lo + base);
    for (int f = threadIdx.x; f < FF / 4; f += 256) {
        float4 g = G4[f], u = U4[f];
        float a0 = g.x / (1.f + __expf(-g.x)) * u.x;
        float a1 = g.y / (1.f + __expf(-g.y)) * u.y;
        float a2 = g.z / (1.f + __expf(-g.z)) * u.z;
        float a3 = g.w / (1.f + __expf(-g.w)) * u.w;
        bf16 h0, l0, h1, l1, h2, l2, h3, l3;
        split_bf(a0, h0, l0); split_bf(a1, h1, l1);
        split_bf(a2, h2, l2); split_bf(a3, h3, l3);
        AH[f] = pack4(h0, h1, h2, h3);
        AL[f] = pack4(l0, l1, l2, l3);
    }
}

// ---------------------------------------------------------------------------
// Final combine
// ---------------------------------------------------------------------------
__global__ void __launch_bounds__(256) k_combine(float* __restrict__ out) {
    int t = blockIdx.x, i = threadIdx.x;
    int e0 = g_tok_e[t * 2],     i0 = g_tok_i[t * 2];     float w0 = g_tok_w[t * 2];
    int e1 = g_tok_e[t * 2 + 1], i1 = g_tok_i[t * 2 + 1]; float w1 = g_tok_w[t * 2 + 1];
    const float4* o0 = (const float4*)(g_O + ((size_t)e0 * NT + i0) * DD);
    const float4* o1 = (const float4*)(g_O + ((size_t)e1 * NT + i1) * DD);
    const float4* rr = (const float4*)(g_res2 + (size_t)t * DD);
    float4 a = rr[i], x = o0[i], y = o1[i], o;
    o.x = fminf(fmaxf(a.x + w0 * x.x + w1 * y.x, -100.f), 100.f);
    o.y = fminf(fmaxf(a.y + w0 * x.y + w1 * y.y, -100.f), 100.f);
    o.z = fminf(fmaxf(a.z + w0 * x.z + w1 * y.z, -100.f), 100.f);
    o.w = fminf(fmaxf(a.w + w0 * x.w + w1 * y.w, -100.f), 100.f);
    ((float4*)(out + (size_t)t * DD))[i] = o;
}

// ---------------------------------------------------------------------------
// Host launcher
// ---------------------------------------------------------------------------
extern "C" void kernel_launch(void* const* d_in, const int* in_sizes, int n_in,
                              void* d_out, int out_size) {
    const float* hidden = (const float*)d_in[0];
    const float* ln1    = (const float*)d_in[1];
    const float* ln2    = (const float*)d_in[2];
    const float* Wq     = (const float*)d_in[3];
    const float* Wk     = (const float*)d_in[4];
    const float* Wv     = (const float*)d_in[5];
    const float* Wo     = (const float*)d_in[6];
    const float* Wr     = (const float*)d_in[7];
    const float* Wg     = (const float*)d_in[8];
    const float* Wu     = (const float*)d_in[9];
    const float* Wd     = (const float*)d_in[10];
    float* out = (float*)d_out;
    (void)in_sizes; (void)n_in; (void)out_size;

    float *p_q, *p_k, *p_v, *p_attn, *p_G, *p_U, *p_O;
    int *p_lst, *p_cnt;
    bf16 *p_h1h, *p_h1l, *p_cth, *p_ctl, *p_fh, *p_fl, *p_ah, *p_al;
    bf16 *p_wqh, *p_wql, *p_wkh, *p_wkl, *p_wvh, *p_wvl, *p_woh, *p_wol;
    bf16 *p_wgh, *p_wgl, *p_wuh, *p_wul, *p_wdh, *p_wdl;
    cudaGetSymbolAddress((void**)&p_q,   g_q);
    cudaGetSymbolAddress((void**)&p_k,   g_k);
    cudaGetSymbolAddress((void**)&p_v,   g_v);
    cudaGetSymbolAddress((void**)&p_attn,g_attn);
    cudaGetSymbolAddress((void**)&p_G,   g_G);
    cudaGetSymbolAddress((void**)&p_U,   g_U);
    cudaGetSymbolAddress((void**)&p_O,   g_O);
    cudaGetSymbolAddress((void**)&p_lst, g_list);
    cudaGetSymbolAddress((void**)&p_cnt, g_cnt);
    cudaGetSymbolAddress((void**)&p_h1h, g_h1_hi);
    cudaGetSymbolAddress((void**)&p_h1l, g_h1_lo);
    cudaGetSymbolAddress((void**)&p_cth, g_ctx_hi);
    cudaGetSymbolAddress((void**)&p_ctl, g_ctx_lo);
    cudaGetSymbolAddress((void**)&p_fh,  g_flat_hi);
    cudaGetSymbolAddress((void**)&p_fl,  g_flat_lo);
    cudaGetSymbolAddress((void**)&p_ah,  g_act_hi);
    cudaGetSymbolAddress((void**)&p_al,  g_act_lo);
    cudaGetSymbolAddress((void**)&p_wqh, g_wqT_hi);
    cudaGetSymbolAddress((void**)&p_wql, g_wqT_lo);
    cudaGetSymbolAddress((void**)&p_wkh, g_wkT_hi);
    cudaGetSymbolAddress((void**)&p_wkl, g_wkT_lo);
    cudaGetSymbolAddress((void**)&p_wvh, g_wvT_hi);
    cudaGetSymbolAddress((void**)&p_wvl, g_wvT_lo);
    cudaGetSymbolAddress((void**)&p_woh, g_woT_hi);
    cudaGetSymbolAddress((void**)&p_wol, g_woT_lo);
    cudaGetSymbolAddress((void**)&p_wgh, g_wgT_hi);
    cudaGetSymbolAddress((void**)&p_wgl, g_wgT_lo);
    cudaGetSymbolAddress((void**)&p_wuh, g_wuT_hi);
    cudaGetSymbolAddress((void**)&p_wul, g_wuT_lo);
    cudaGetSymbolAddress((void**)&p_wdh, g_wdT_hi);
    cudaGetSymbolAddress((void**)&p_wdl, g_wdT_lo);

    k_zero_init<<<1, 32>>>();

    // Weight transpose + bf16 split (attention + MoE)
    k_wt<<<dim3(DD / 32, DD / 32, 1), 256>>>(Wq, p_wqh, p_wql, DD, DD, 0, 0);
    k_wt<<<dim3(KVD / 32, DD / 32, 1), 256>>>(Wk, p_wkh, p_wkl, DD, KVD, 0, 0);
    k_wt<<<dim3(KVD / 32, DD / 32, 1), 256>>>(Wv, p_wvh, p_wvl, DD, KVD, 0, 0);
    k_wt<<<dim3(DD / 32, DD / 32, 1), 256>>>(Wo, p_woh, p_wol, DD, DD, 0, 0);
    k_wt<<<dim3(FF / 32, DD / 32, NEXP), 256>>>(Wg, p_wgh, p_wgl, DD, FF,
                                                (size_t)DD * FF, (size_t)FF * DD);
    k_wt<<<dim3(FF / 32, DD / 32, NEXP), 256>>>(Wu, p_wuh, p_wul, DD, FF,
                                                (size_t)DD * FF, (size_t)FF * DD);
    k_wt<<<dim3(DD / 32, FF / 32, NEXP), 256>>>(Wd, p_wdh, p_wdl, FF, DD,
                                                (size_t)FF * DD, (size_t)DD * FF);

    k_rms1<<<NT, 256>>>(hidden, ln1);

    // QKV on tensor cores
    k_mma_gemm<<<dim3(DD / 128, NT / 128, 1), 256>>>(
        p_h1h, p_h1l, DD, 0, p_wqh, p_wql, 0, p_q, DD, 0, NT, DD, 0, 0);
    k_mma_gemm<<<dim3(KVD / 128, NT / 128, 1), 256>>>(
        p_h1h, p_h1l, DD, 0, p_wkh, p_wkl, 0, p_k, KVD, 0, NT, DD, 0, 0);
    k_mma_gemm<<<dim3(KVD / 128, NT / 128, 1), 256>>>(
        p_h1h, p_h1l, DD, 0, p_wvh, p_wvl, 0, p_v, KVD, 0, NT, DD, 0, 0);

    k_rope_q<<<NT, 512>>>();
    k_rope_k<<<NT, 128>>>();
    k_cvt_v<<<NT * KVD / 1024, 256>>>();

    // Attention on tensor cores
    k_attn_mma<<<dim3(SS / 64, 32), 128>>>();

    // Wo on tensor cores
    k_mma_gemm<<<dim3(DD / 128, NT / 128, 1), 256>>>(
        p_cth, p_ctl, DD, 0, p_woh, p_wol, 0, p_attn, DD, 0, NT, DD, 0, 0);

    k_post<<<NT, 256>>>(hidden, ln2);
    k_router<<<NT, 256>>>(Wr);

    // MoE on tensor cores
    k_mma_gemm<<<dim3(FF / 128, NT / 128, NEXP), 256>>>(
        p_fh, p_fl, DD, 0, p_wgh, p_wgl, (size_t)FF * DD,
        p_G, FF, (size_t)NT * FF, 0, DD, p_lst, p_cnt);
    k_mma_gemm<<<dim3(FF / 128, NT / 128, NEXP), 256>>>(
        p_fh, p_fl, DD, 0, p_wuh, p_wul, (size_t)FF * DD,
        p_U, FF, (size_t)NT * FF, 0, DD, p_lst, p_cnt);
    k_act<<<dim3(NT, NEXP), 256>>>();
    k_mma_gemm<<<dim3(DD / 128, NT / 128, NEXP), 256>>>(
        p_ah, p_al, FF, (size_t)NT * FF, p_wdh, p_wdl, (size_t)DD * FF,
        p_O, DD, (size_t)NT * DD, 0, FF, 0, p_cnt);

    k_combine<<<NT, 256>>>(out);
}